// round 4
// baseline (speedup 1.0000x reference)
#include <cuda_runtime.h>
#include <cuda_bf16.h>
#include <math.h>
#include <stdint.h>

// Problem constants
#define HIDDEN 128
#define STATE  256
#define SEQ    4096
#define BATCH  16
#define TROWS  (BATCH * SEQ)      // 65536
#define LC     128                // scan chunk length == GEMM M-tile
#define NCHUNK (SEQ / LC)         // 32 chunks per sequence

// ---------------------------------------------------------------------------
// Scratch (static device globals — no allocations allowed)
// ---------------------------------------------------------------------------
__device__ float g_ys[(size_t)TROWS * STATE];   // LOCAL scan trajectory y_loc
__device__ float g_coef[STATE * 4];             // a,b,c,d  (M)
__device__ float g_mp64[STATE * 4];             // M^64
__device__ float g_mp  [STATE * 4];             // M^128
__device__ float g_step[STATE];
__device__ float g_carry[(size_t)BATCH * NCHUNK * STATE * 2]; // (z,y) per chunk

// bf16 hi/lo split weights
__device__ __nv_bfloat16 g_B1hi[STATE * HIDDEN];  // step-scaled B
__device__ __nv_bfloat16 g_B1lo[STATE * HIDDEN];
__device__ __nv_bfloat16 g_Chi [HIDDEN * STATE];
__device__ __nv_bfloat16 g_Clo [HIDDEN * STATE];

// ---------------------------------------------------------------------------
// Helpers
// ---------------------------------------------------------------------------
__device__ __forceinline__ uint32_t smem_u32(const void* p) {
    uint32_t a;
    asm("{ .reg .u64 t; cvta.to.shared.u64 t, %1; cvt.u32.u64 %0, t; }"
        : "=r"(a) : "l"(p));
    return a;
}
__device__ __forceinline__ uint32_t pack_bf16(__nv_bfloat16 a, __nv_bfloat16 b) {
    return (uint32_t)__bfloat16_as_ushort(a) | ((uint32_t)__bfloat16_as_ushort(b) << 16);
}
__device__ __forceinline__ void split2(float v, __nv_bfloat16& h, __nv_bfloat16& l) {
    h = __float2bfloat16(v);
    l = __float2bfloat16(v - __bfloat162float(h));
}

#define LDSM_X4(r0, r1, r2, r3, addr)                                          \
    asm volatile("ldmatrix.sync.aligned.m8n8.x4.shared.b16 {%0,%1,%2,%3}, [%4];" \
        : "=r"(r0), "=r"(r1), "=r"(r2), "=r"(r3) : "r"(addr))

#define MMA_BF16(d, a, b)                                                      \
    asm volatile("mma.sync.aligned.m16n8k16.row.col.f32.bf16.bf16.f32 "        \
        "{%0,%1,%2,%3}, {%4,%5,%6,%7}, {%8,%9}, {%0,%1,%2,%3};"                \
        : "+f"((d)[0]), "+f"((d)[1]), "+f"((d)[2]), "+f"((d)[3])               \
        : "r"((a)[0]), "r"((a)[1]), "r"((a)[2]), "r"((a)[3]),                  \
          "r"((b)[0]), "r"((b)[1]))

#define SPB 272          // padded SMEM row stride in bytes (136 bf16)
#define KH 128           // K chunk processed per staging pass
#define UST 129          // u-tile stride (floats), [state][t] layout
#define FST 132          // fix-tile stride (floats), [t][state_local] layout

// ---------------------------------------------------------------------------
// Prep: per-state coefficients, M^64 and M^128 by squaring
// ---------------------------------------------------------------------------
__global__ void prep_kernel(const float* __restrict__ A_diag,
                            const float* __restrict__ steps)
{
    int n = threadIdx.x;
    float st   = 1.0f / (1.0f + expf(-steps[n]));
    float Av   = fmaxf(A_diag[n], 0.0f);
    float s2A  = st * st * Av;
    float schur = 1.0f / (1.0f + s2A);
    float a = 1.0f - s2A * schur;
    float b = -st * Av * schur;
    float c = st * schur;
    float d = schur;

    g_step[n] = st;
    g_coef[n*4+0] = a; g_coef[n*4+1] = b; g_coef[n*4+2] = c; g_coef[n*4+3] = d;

    float pa = a, pb = b, pc = c, pd = d;
    #pragma unroll
    for (int i = 0; i < 6; i++) {       // M^64
        float qa = pa*pa + pb*pc;
        float qb = pa*pb + pb*pd;
        float qc = pc*pa + pd*pc;
        float qd = pc*pb + pd*pd;
        pa = qa; pb = qb; pc = qc; pd = qd;
    }
    g_mp64[n*4+0] = pa; g_mp64[n*4+1] = pb; g_mp64[n*4+2] = pc; g_mp64[n*4+3] = pd;
    {                                    // M^128
        float qa = pa*pa + pb*pc;
        float qb = pa*pb + pb*pd;
        float qc = pc*pa + pd*pc;
        float qd = pc*pb + pd*pd;
        pa = qa; pb = qb; pc = qc; pd = qd;
    }
    g_mp[n*4+0] = pa; g_mp[n*4+1] = pb; g_mp[n*4+2] = pc; g_mp[n*4+3] = pd;
}

// Weight conversion: step*B and C into bf16 hi/lo
__global__ void wconv_kernel(const float* __restrict__ Bw,
                             const float* __restrict__ Cw)
{
    int idx = blockIdx.x * 256 + threadIdx.x;
    if (idx < STATE * HIDDEN) {
        int n = idx >> 7;
        float v = g_step[n] * Bw[idx];
        __nv_bfloat16 h, l; split2(v, h, l);
        g_B1hi[idx] = h; g_B1lo[idx] = l;
    } else {
        int j = idx - STATE * HIDDEN;
        __nv_bfloat16 h, l; split2(Cw[j], h, l);
        g_Chi[j] = h; g_Clo[j] = l;
    }
}

// ---------------------------------------------------------------------------
// K1: GEMM1 (u = x @ (step*B)^T, bf16x3) fused with local chunk scan.
// CTA = 128 rows (one chunk), N=256 states resident, K=128 single pass.
// After MMAs: u tile -> SMEM [state][t] (stride 129), 256 lanes scan 128
// steps each, writing y_loc to g_ys and end-state to g_carry.
// ---------------------------------------------------------------------------
__global__ void __launch_bounds__(256, 1)
gemm1_scan_kernel(const float* __restrict__ A,
                  const __nv_bfloat16* __restrict__ Whi,
                  const __nv_bfloat16* __restrict__ Wlo)
{
    constexpr int N = 256, KFULL = 128;
    constexpr int WN = N / 4;          // 64
    constexpr int MI = 4;
    constexpr int NI = WN / 8;         // 8
    constexpr uint32_t SA_HI = 0;
    constexpr uint32_t SA_LO = 128u * SPB;
    constexpr uint32_t SW_HI = 2u * 128u * SPB;
    constexpr uint32_t SW_LO = SW_HI + (uint32_t)N * SPB;

    extern __shared__ char dsm_raw[];
    char* dsm = (char*)(((uintptr_t)dsm_raw + 1023) & ~(uintptr_t)1023);
    const uint32_t dbase = smem_u32(dsm);

    const int tid  = threadIdx.x;
    const int lane = tid & 31;
    const int w    = tid >> 5;
    const int row0 = blockIdx.x * 128;
    const int warp_m = (w & 1) * 64;
    const int warp_n = (w >> 1) * WN;

    const int a_row = (lane & 7) + ((lane >> 3) & 1) * 8;
    const int a_k8  = (lane >> 4) * 8;
    const int b_row = (lane & 7) + (lane >> 4) * 8;
    const int b_k8  = ((lane >> 3) & 1) * 8;

    float acc[MI][NI][4];
    #pragma unroll
    for (int mi = 0; mi < MI; mi++)
        #pragma unroll
        for (int ni = 0; ni < NI; ni++)
            #pragma unroll
            for (int q = 0; q < 4; q++)
                acc[mi][ni][q] = 0.0f;

    // ---- stage A (x) : fp32 -> bf16 hi/lo ----
    #pragma unroll
    for (int it = 0; it < 16; it++) {
        int idx = tid + it * 256;
        int r   = idx >> 5;
        int k   = (idx & 31) * 4;
        float4 v = *(const float4*)(A + (size_t)(row0 + r) * KFULL + k);
        __nv_bfloat16 h0,l0,h1,l1,h2,l2,h3,l3;
        split2(v.x,h0,l0); split2(v.y,h1,l1); split2(v.z,h2,l2); split2(v.w,h3,l3);
        uint32_t o = (uint32_t)r * SPB + (uint32_t)k * 2;
        *(uint32_t*)(dsm + SA_HI + o)     = pack_bf16(h0, h1);
        *(uint32_t*)(dsm + SA_HI + o + 4) = pack_bf16(h2, h3);
        *(uint32_t*)(dsm + SA_LO + o)     = pack_bf16(l0, l1);
        *(uint32_t*)(dsm + SA_LO + o + 4) = pack_bf16(l2, l3);
    }
    // ---- stage W (step*B) hi/lo ----
    #pragma unroll
    for (int it = 0; it < N / 8; it++) {
        int idx  = tid + it * 256;
        int half = idx / (N * 16);
        int rem  = idx - half * (N * 16);
        int r    = rem >> 4;
        int k8   = (rem & 15) * 8;
        const __nv_bfloat16* src = half ? Wlo : Whi;
        uint4 v = *(const uint4*)(src + (size_t)r * KFULL + k8);
        uint32_t o = (half ? SW_LO : SW_HI) + (uint32_t)r * SPB + (uint32_t)k8 * 2;
        *(uint4*)(dsm + o) = v;
    }
    __syncthreads();

    // ---- 3 passes: Ahi*Whi, Ahi*Wlo, Alo*Whi ----
    #pragma unroll
    for (int pass = 0; pass < 3; pass++) {
        const uint32_t Abase = dbase + (pass == 2 ? SA_LO : SA_HI);
        const uint32_t Wbase = dbase + (pass == 1 ? SW_LO : SW_HI);
        #pragma unroll
        for (int kk = 0; kk < KH / 16; kk++) {
            const int k0 = kk * 16;
            uint32_t af[MI][4];
            #pragma unroll
            for (int mi = 0; mi < MI; mi++) {
                uint32_t addr = Abase
                    + (uint32_t)(warp_m + mi * 16 + a_row) * SPB
                    + (uint32_t)(k0 + a_k8) * 2;
                LDSM_X4(af[mi][0], af[mi][1], af[mi][2], af[mi][3], addr);
            }
            uint32_t bf[NI][2];
            #pragma unroll
            for (int nj = 0; nj < NI / 2; nj++) {
                uint32_t addr = Wbase
                    + (uint32_t)(warp_n + nj * 16 + b_row) * SPB
                    + (uint32_t)(k0 + b_k8) * 2;
                uint32_t r0, r1, r2, r3;
                LDSM_X4(r0, r1, r2, r3, addr);
                bf[nj*2+0][0] = r0; bf[nj*2+0][1] = r1;
                bf[nj*2+1][0] = r2; bf[nj*2+1][1] = r3;
            }
            #pragma unroll
            for (int mi = 0; mi < MI; mi++)
                #pragma unroll
                for (int ni = 0; ni < NI; ni++)
                    MMA_BF16(acc[mi][ni], af[mi], bf[ni]);
        }
    }

    // ---- dump u tile to SMEM, transposed [state][t], stride UST ----
    __syncthreads();   // staging reads done; reuse SMEM
    float* su = (float*)dsm;
    #pragma unroll
    for (int mi = 0; mi < MI; mi++) {
        const int r = warp_m + mi * 16 + (lane >> 2);
        #pragma unroll
        for (int ni = 0; ni < NI; ni++) {
            const int c = warp_n + ni * 8 + (lane & 3) * 2;
            su[(size_t)c * UST + r]           = acc[mi][ni][0];
            su[(size_t)(c + 1) * UST + r]     = acc[mi][ni][1];
            su[(size_t)c * UST + r + 8]       = acc[mi][ni][2];
            su[(size_t)(c + 1) * UST + r + 8] = acc[mi][ni][3];
        }
    }
    __syncthreads();

    // ---- local scan: 256 lanes, one state each, 128 steps from zero ----
    {
        const int n = tid;
        const float4 cf = *(const float4*)&g_coef[n * 4];
        float* yout = g_ys + (size_t)row0 * STATE + n;
        const float* un = su + (size_t)n * UST;
        float z = 0.0f, y = 0.0f;
        #pragma unroll 4
        for (int t = 0; t < LC; t++) {
            float u  = un[t];
            float zu = z + u;
            float zn = fmaf(cf.x, zu, cf.y * y);
            float yn = fmaf(cf.z, zu, cf.w * y);
            z = zn; y = yn;
            yout[(size_t)t * STATE] = y;
        }
        ((float2*)g_carry)[(size_t)blockIdx.x * STATE + n] = make_float2(z, y);
    }
}

// ---------------------------------------------------------------------------
// K2: scan across chunk end-states (M^128); rewrite carries to carry-INs.
// ---------------------------------------------------------------------------
__global__ void __launch_bounds__(256) scan_phase2_kernel()
{
    int n = threadIdx.x;
    int b = blockIdx.x;
    const float4 mp = *(const float4*)&g_mp[n * 4];

    float z = 0.0f, y = 0.0f;
    for (int c = 0; c < NCHUNK; c++) {
        size_t idx = ((size_t)b * NCHUNK + c) * STATE + n;
        float2 e = ((float2*)g_carry)[idx];
        ((float2*)g_carry)[idx] = make_float2(z, y);
        float zn = fmaf(mp.x, z, fmaf(mp.y, y, e.x));
        float yn = fmaf(mp.z, z, fmaf(mp.w, y, e.y));
        z = zn; y = yn;
    }
}

// ---------------------------------------------------------------------------
// K3: fix-up + GEMM2 (out = ys @ C^T + D*x, bf16x3).
// ys_corrected[t][n] = y_loc[t][n] + (M^{t+1} s0(n)).y  — fix computed in
// SMEM per K-half (128 states), added during A staging. K=256 in 2 halves.
// ---------------------------------------------------------------------------
__global__ void __launch_bounds__(256, 1)
fix_gemm2_kernel(float* __restrict__ Cout,
                 const __nv_bfloat16* __restrict__ Whi,
                 const __nv_bfloat16* __restrict__ Wlo,
                 const float* __restrict__ xin,
                 const float* __restrict__ Dv)
{
    constexpr int N = 128, KFULL = 256;
    constexpr int WN = N / 4;          // 32
    constexpr int MI = 4;
    constexpr int NI = WN / 8;         // 4
    constexpr uint32_t SA_HI = 0;
    constexpr uint32_t SA_LO = 128u * SPB;                   // 34816
    constexpr uint32_t SW_HI = 2u * 128u * SPB;              // 69632
    constexpr uint32_t SW_LO = SW_HI + (uint32_t)N * SPB;    // 104448
    constexpr uint32_t SFIX  = SW_LO + (uint32_t)N * SPB;    // 139264

    extern __shared__ char dsm_raw[];
    char* dsm = (char*)(((uintptr_t)dsm_raw + 1023) & ~(uintptr_t)1023);
    const uint32_t dbase = smem_u32(dsm);
    float* sfix = (float*)(dsm + SFIX);

    const int tid  = threadIdx.x;
    const int lane = tid & 31;
    const int w    = tid >> 5;
    const int row0 = blockIdx.x * 128;
    const int warp_m = (w & 1) * 64;
    const int warp_n = (w >> 1) * WN;

    const int a_row = (lane & 7) + ((lane >> 3) & 1) * 8;
    const int a_k8  = (lane >> 4) * 8;
    const int b_row = (lane & 7) + (lane >> 4) * 8;
    const int b_k8  = ((lane >> 3) & 1) * 8;

    float acc[MI][NI][4];
    #pragma unroll
    for (int mi = 0; mi < MI; mi++)
        #pragma unroll
        for (int ni = 0; ni < NI; ni++)
            #pragma unroll
            for (int q = 0; q < 4; q++)
                acc[mi][ni][q] = 0.0f;

    for (int h = 0; h < 2; h++) {
        const int kh0 = h * KH;
        __syncthreads();   // previous half fully consumed

        // ---- fix-up: fix[t][nl] = (M^{t+1} s0).y for states of this half ----
        {
            const int nl = tid & 127;
            const int j  = tid >> 7;          // time half: 0 -> t 0..63, 1 -> 64..127
            const int n  = kh0 + nl;
            float2 s0 = ((float2*)g_carry)[(size_t)blockIdx.x * STATE + n];
            const float4 cf = *(const float4*)&g_coef[n * 4];
            float z, y;
            if (j == 0) { z = s0.x; y = s0.y; }
            else {
                const float4 m6 = *(const float4*)&g_mp64[n * 4];
                z = fmaf(m6.x, s0.x, m6.y * s0.y);
                y = fmaf(m6.z, s0.x, m6.w * s0.y);
            }
            float* fp = sfix + (size_t)(j * 64) * FST + nl;
            #pragma unroll 4
            for (int t = 0; t < 64; t++) {
                float zn = fmaf(cf.x, z, cf.y * y);
                float yn = fmaf(cf.z, z, cf.w * y);
                z = zn; y = yn;
                fp[(size_t)t * FST] = y;
            }
        }
        __syncthreads();

        // ---- stage A: y_loc + fix -> bf16 hi/lo ----
        #pragma unroll
        for (int it = 0; it < 16; it++) {
            int idx = tid + it * 256;
            int r   = idx >> 5;
            int k   = (idx & 31) * 4;
            float4 v = *(const float4*)(g_ys + (size_t)(row0 + r) * KFULL + kh0 + k);
            const float4 f = *(const float4*)(sfix + (size_t)r * FST + k);
            v.x += f.x; v.y += f.y; v.z += f.z; v.w += f.w;
            __nv_bfloat16 h0,l0,h1,l1,h2,l2,h3,l3;
            split2(v.x,h0,l0); split2(v.y,h1,l1); split2(v.z,h2,l2); split2(v.w,h3,l3);
            uint32_t o = (uint32_t)r * SPB + (uint32_t)k * 2;
            *(uint32_t*)(dsm + SA_HI + o)     = pack_bf16(h0, h1);
            *(uint32_t*)(dsm + SA_HI + o + 4) = pack_bf16(h2, h3);
            *(uint32_t*)(dsm + SA_LO + o)     = pack_bf16(l0, l1);
            *(uint32_t*)(dsm + SA_LO + o + 4) = pack_bf16(l2, l3);
        }
        // ---- stage W (C) hi/lo ----
        #pragma unroll
        for (int it = 0; it < N / 8; it++) {
            int idx  = tid + it * 256;
            int half = idx / (N * 16);
            int rem  = idx - half * (N * 16);
            int r    = rem >> 4;
            int k8   = (rem & 15) * 8;
            const __nv_bfloat16* src = half ? Wlo : Whi;
            uint4 v = *(const uint4*)(src + (size_t)r * KFULL + kh0 + k8);
            uint32_t o = (half ? SW_LO : SW_HI) + (uint32_t)r * SPB + (uint32_t)k8 * 2;
            *(uint4*)(dsm + o) = v;
        }
        __syncthreads();

        // ---- 3 passes ----
        #pragma unroll
        for (int pass = 0; pass < 3; pass++) {
            const uint32_t Abase = dbase + (pass == 2 ? SA_LO : SA_HI);
            const uint32_t Wbase = dbase + (pass == 1 ? SW_LO : SW_HI);
            #pragma unroll
            for (int kk = 0; kk < KH / 16; kk++) {
                const int k0 = kk * 16;
                uint32_t af[MI][4];
                #pragma unroll
                for (int mi = 0; mi < MI; mi++) {
                    uint32_t addr = Abase
                        + (uint32_t)(warp_m + mi * 16 + a_row) * SPB
                        + (uint32_t)(k0 + a_k8) * 2;
                    LDSM_X4(af[mi][0], af[mi][1], af[mi][2], af[mi][3], addr);
                }
                uint32_t bf[NI][2];
                #pragma unroll
                for (int nj = 0; nj < NI / 2; nj++) {
                    uint32_t addr = Wbase
                        + (uint32_t)(warp_n + nj * 16 + b_row) * SPB
                        + (uint32_t)(k0 + b_k8) * 2;
                    uint32_t r0, r1, r2, r3;
                    LDSM_X4(r0, r1, r2, r3, addr);
                    bf[nj*2+0][0] = r0; bf[nj*2+0][1] = r1;
                    bf[nj*2+1][0] = r2; bf[nj*2+1][1] = r3;
                }
                #pragma unroll
                for (int mi = 0; mi < MI; mi++)
                    #pragma unroll
                    for (int ni = 0; ni < NI; ni++)
                        MMA_BF16(acc[mi][ni], af[mi], bf[ni]);
            }
        }
    }

    // ---- epilogue with D*x ----
    const int rbase = row0 + warp_m + (lane >> 2);
    const int cbase = warp_n + (lane & 3) * 2;
    #pragma unroll
    for (int ni = 0; ni < NI; ni++) {
        const int col = cbase + ni * 8;
        const float d0 = Dv[col], d1 = Dv[col + 1];
        #pragma unroll
        for (int mi = 0; mi < MI; mi++) {
            const int r0 = rbase + mi * 16;
            float* p0 = Cout + (size_t)r0 * N + col;
            float* p1 = Cout + (size_t)(r0 + 8) * N + col;
            const float2 x0 = *(const float2*)(xin + (size_t)r0 * N + col);
            const float2 x1 = *(const float2*)(xin + (size_t)(r0 + 8) * N + col);
            float2 o0 = make_float2(fmaf(d0, x0.x, acc[mi][ni][0]),
                                    fmaf(d1, x0.y, acc[mi][ni][1]));
            float2 o1 = make_float2(fmaf(d0, x1.x, acc[mi][ni][2]),
                                    fmaf(d1, x1.y, acc[mi][ni][3]));
            *(float2*)p0 = o0;
            *(float2*)p1 = o1;
        }
    }
}

// ---------------------------------------------------------------------------
// kernel_launch
// Inputs: x[16,4096,128], A_diag[256], steps[256], B[256,128], C[128,256], D[128]
// ---------------------------------------------------------------------------
extern "C" void kernel_launch(void* const* d_in, const int* in_sizes, int n_in,
                              void* d_out, int out_size)
{
    const float* x      = (const float*)d_in[0];
    const float* A_diag = (const float*)d_in[1];
    const float* steps  = (const float*)d_in[2];
    const float* Bw     = (const float*)d_in[3];
    const float* Cw     = (const float*)d_in[4];
    const float* Dv     = (const float*)d_in[5];
    float* out = (float*)d_out;

    __nv_bfloat16 *b1hi, *b1lo, *chi, *clo;
    cudaGetSymbolAddress((void**)&b1hi, g_B1hi);
    cudaGetSymbolAddress((void**)&b1lo, g_B1lo);
    cudaGetSymbolAddress((void**)&chi,  g_Chi);
    cudaGetSymbolAddress((void**)&clo,  g_Clo);

    // K1 SMEM: A(2*128*272) + W(2*256*272) = 208896 (+1024 align slack)
    // K3 SMEM: A(2*128*272) + W(2*128*272) + fix(128*132*4) = 206848 (+1024)
    const int smem1 = 1024 + 2 * 128 * SPB + 2 * 256 * SPB;   // 209920
    const int smem3 = 1024 + 2 * 128 * SPB + 2 * 128 * SPB + 128 * FST * 4; // 207872
    cudaFuncSetAttribute(gemm1_scan_kernel,
                         cudaFuncAttributeMaxDynamicSharedMemorySize, smem1);
    cudaFuncSetAttribute(fix_gemm2_kernel,
                         cudaFuncAttributeMaxDynamicSharedMemorySize, smem3);

    // 1. coefficients + weight bf16 split
    prep_kernel<<<1, 256>>>(A_diag, steps);
    wconv_kernel<<<(STATE * HIDDEN + HIDDEN * STATE) / 256, 256>>>(Bw, Cw);

    // 2. GEMM1 + local scan  (writes y_loc + chunk end-states)
    gemm1_scan_kernel<<<TROWS / 128, 256, smem1>>>(x, b1hi, b1lo);

    // 3. cross-chunk scan (carry-ins)
    scan_phase2_kernel<<<BATCH, 256>>>();

    // 4. fix-up + GEMM2 (+ D*x)
    fix_gemm2_kernel<<<TROWS / 128, 256, smem3>>>(out, chi, clo, x, Dv);
}

// round 5
// speedup vs baseline: 1.0641x; 1.0641x over previous
#include <cuda_runtime.h>
#include <cuda_bf16.h>
#include <math.h>
#include <stdint.h>

// Problem constants
#define HIDDEN 128
#define STATE  256
#define SEQ    4096
#define BATCH  16
#define TROWS  (BATCH * SEQ)      // 65536
#define LC     128                // scan chunk length == GEMM M-tile
#define NCHUNK (SEQ / LC)         // 32 chunks per sequence
#define NTILE  (TROWS / 128)      // 512 CTAs

// ---------------------------------------------------------------------------
// Scratch (static device globals — no allocations allowed)
// ---------------------------------------------------------------------------
__device__ float g_ys[(size_t)TROWS * STATE];   // piecewise-LOCAL scan y
__device__ float g_coef[STATE * 4];             // a,b,c,d  (M)
__device__ float g_mp32[STATE * 4];             // M^32
__device__ float g_mp64[STATE * 4];             // M^64
__device__ float g_mp  [STATE * 4];             // M^128
__device__ float g_step[STATE];
__device__ float g_carry[(size_t)NTILE * STATE * 2]; // per-chunk (z,y)
__device__ float g_e1   [(size_t)NTILE * STATE * 2]; // first-half local ends

// bf16 hi/lo split weights
__device__ __nv_bfloat16 g_B1hi[STATE * HIDDEN];  // step-scaled B
__device__ __nv_bfloat16 g_B1lo[STATE * HIDDEN];
__device__ __nv_bfloat16 g_Chi [HIDDEN * STATE];
__device__ __nv_bfloat16 g_Clo [HIDDEN * STATE];

// ---------------------------------------------------------------------------
// Helpers
// ---------------------------------------------------------------------------
__device__ __forceinline__ uint32_t smem_u32(const void* p) {
    uint32_t a;
    asm("{ .reg .u64 t; cvta.to.shared.u64 t, %1; cvt.u32.u64 %0, t; }"
        : "=r"(a) : "l"(p));
    return a;
}
__device__ __forceinline__ uint32_t pack_bf16(__nv_bfloat16 a, __nv_bfloat16 b) {
    return (uint32_t)__bfloat16_as_ushort(a) | ((uint32_t)__bfloat16_as_ushort(b) << 16);
}
__device__ __forceinline__ void split2(float v, __nv_bfloat16& h, __nv_bfloat16& l) {
    h = __float2bfloat16(v);
    l = __float2bfloat16(v - __bfloat162float(h));
}

#define LDSM_X4(r0, r1, r2, r3, addr)                                          \
    asm volatile("ldmatrix.sync.aligned.m8n8.x4.shared.b16 {%0,%1,%2,%3}, [%4];" \
        : "=r"(r0), "=r"(r1), "=r"(r2), "=r"(r3) : "r"(addr))

#define MMA_BF16(d, a, b)                                                      \
    asm volatile("mma.sync.aligned.m16n8k16.row.col.f32.bf16.bf16.f32 "        \
        "{%0,%1,%2,%3}, {%4,%5,%6,%7}, {%8,%9}, {%0,%1,%2,%3};"                \
        : "+f"((d)[0]), "+f"((d)[1]), "+f"((d)[2]), "+f"((d)[3])               \
        : "r"((a)[0]), "r"((a)[1]), "r"((a)[2]), "r"((a)[3]),                  \
          "r"((b)[0]), "r"((b)[1]))

#define SPB 272          // padded SMEM row stride in bytes (136 bf16)
#define KH 128           // K chunk processed per staging pass
#define UST 129          // u-tile stride (floats), [state][t]
#define FST 132          // fix-tile stride (floats), [t][state_local]

// ---------------------------------------------------------------------------
// Prep: per-state coefficients, M^32 / M^64 / M^128 by squaring
// ---------------------------------------------------------------------------
__global__ void prep_kernel(const float* __restrict__ A_diag,
                            const float* __restrict__ steps)
{
    int n = threadIdx.x;
    float st   = 1.0f / (1.0f + expf(-steps[n]));
    float Av   = fmaxf(A_diag[n], 0.0f);
    float s2A  = st * st * Av;
    float schur = 1.0f / (1.0f + s2A);
    float a = 1.0f - s2A * schur;
    float b = -st * Av * schur;
    float c = st * schur;
    float d = schur;

    g_step[n] = st;
    g_coef[n*4+0] = a; g_coef[n*4+1] = b; g_coef[n*4+2] = c; g_coef[n*4+3] = d;

    float pa = a, pb = b, pc = c, pd = d;
    #pragma unroll
    for (int i = 0; i < 5; i++) {        // M^32
        float qa = pa*pa + pb*pc;
        float qb = pa*pb + pb*pd;
        float qc = pc*pa + pd*pc;
        float qd = pc*pb + pd*pd;
        pa = qa; pb = qb; pc = qc; pd = qd;
    }
    g_mp32[n*4+0] = pa; g_mp32[n*4+1] = pb; g_mp32[n*4+2] = pc; g_mp32[n*4+3] = pd;
    {                                     // M^64
        float qa = pa*pa + pb*pc;
        float qb = pa*pb + pb*pd;
        float qc = pc*pa + pd*pc;
        float qd = pc*pb + pd*pd;
        pa = qa; pb = qb; pc = qc; pd = qd;
    }
    g_mp64[n*4+0] = pa; g_mp64[n*4+1] = pb; g_mp64[n*4+2] = pc; g_mp64[n*4+3] = pd;
    {                                     // M^128
        float qa = pa*pa + pb*pc;
        float qb = pa*pb + pb*pd;
        float qc = pc*pa + pd*pc;
        float qd = pc*pb + pd*pd;
        pa = qa; pb = qb; pc = qc; pd = qd;
    }
    g_mp[n*4+0] = pa; g_mp[n*4+1] = pb; g_mp[n*4+2] = pc; g_mp[n*4+3] = pd;
}

// Weight conversion: step*B and C into bf16 hi/lo
__global__ void wconv_kernel(const float* __restrict__ Bw,
                             const float* __restrict__ Cw)
{
    int idx = blockIdx.x * 256 + threadIdx.x;
    if (idx < STATE * HIDDEN) {
        int n = idx >> 7;
        float v = g_step[n] * Bw[idx];
        __nv_bfloat16 h, l; split2(v, h, l);
        g_B1hi[idx] = h; g_B1lo[idx] = l;
    } else {
        int j = idx - STATE * HIDDEN;
        __nv_bfloat16 h, l; split2(Cw[j], h, l);
        g_Chi[j] = h; g_Clo[j] = l;
    }
}

// ---------------------------------------------------------------------------
// K1: GEMM1 (u = x @ (step*B)^T, bf16x3) fused with 2-way-split local scan.
// 512 threads. Warp layout 2x8 (warp tile 64x32). After MMAs, u -> SMEM
// [state][t]; 512 lanes = 256 states x 2 time-halves scan 64 steps each.
// y written is local-to-its-half; e1 (first-half end) -> g_e1; chunk end
// = M^64*e1 + e2 -> g_carry.
// ---------------------------------------------------------------------------
__global__ void __launch_bounds__(512, 1)
gemm1_scan_kernel(const float* __restrict__ A,
                  const __nv_bfloat16* __restrict__ Whi,
                  const __nv_bfloat16* __restrict__ Wlo)
{
    constexpr int N = 256, KFULL = 128;
    constexpr int MI = 4;              // 64/16
    constexpr int NI = 4;              // 32/8
    constexpr uint32_t SA_HI = 0;
    constexpr uint32_t SA_LO = 128u * SPB;
    constexpr uint32_t SW_HI = 2u * 128u * SPB;
    constexpr uint32_t SW_LO = SW_HI + (uint32_t)N * SPB;

    extern __shared__ char dsm_raw[];
    char* dsm = (char*)(((uintptr_t)dsm_raw + 1023) & ~(uintptr_t)1023);
    const uint32_t dbase = smem_u32(dsm);

    const int tid  = threadIdx.x;
    const int lane = tid & 31;
    const int w    = tid >> 5;         // 0..15
    const int row0 = blockIdx.x * 128;
    const int warp_m = (w & 1) * 64;
    const int warp_n = (w >> 1) * 32;

    const int a_row = (lane & 7) + ((lane >> 3) & 1) * 8;
    const int a_k8  = (lane >> 4) * 8;
    const int b_row = (lane & 7) + (lane >> 4) * 8;
    const int b_k8  = ((lane >> 3) & 1) * 8;

    float acc[MI][NI][4];
    #pragma unroll
    for (int mi = 0; mi < MI; mi++)
        #pragma unroll
        for (int ni = 0; ni < NI; ni++)
            #pragma unroll
            for (int q = 0; q < 4; q++)
                acc[mi][ni][q] = 0.0f;

    // ---- stage A (x): fp32 -> bf16 hi/lo ----
    #pragma unroll
    for (int it = 0; it < 8; it++) {
        int idx = tid + it * 512;          // 4096 float4s
        int r   = idx >> 5;
        int k   = (idx & 31) * 4;
        float4 v = *(const float4*)(A + (size_t)(row0 + r) * KFULL + k);
        __nv_bfloat16 h0,l0,h1,l1,h2,l2,h3,l3;
        split2(v.x,h0,l0); split2(v.y,h1,l1); split2(v.z,h2,l2); split2(v.w,h3,l3);
        uint32_t o = (uint32_t)r * SPB + (uint32_t)k * 2;
        *(uint32_t*)(dsm + SA_HI + o)     = pack_bf16(h0, h1);
        *(uint32_t*)(dsm + SA_HI + o + 4) = pack_bf16(h2, h3);
        *(uint32_t*)(dsm + SA_LO + o)     = pack_bf16(l0, l1);
        *(uint32_t*)(dsm + SA_LO + o + 4) = pack_bf16(l2, l3);
    }
    // ---- stage W (step*B) hi/lo ----
    #pragma unroll
    for (int it = 0; it < 16; it++) {
        int idx  = tid + it * 512;         // 8192 uint4 (hi+lo)
        int half = idx >> 12;
        int rem  = idx & 4095;
        int r    = rem >> 4;
        int k8   = (rem & 15) * 8;
        const __nv_bfloat16* src = half ? Wlo : Whi;
        uint4 v = *(const uint4*)(src + (size_t)r * KFULL + k8);
        uint32_t o = (half ? SW_LO : SW_HI) + (uint32_t)r * SPB + (uint32_t)k8 * 2;
        *(uint4*)(dsm + o) = v;
    }
    __syncthreads();

    // ---- 3 passes: Ahi*Whi, Ahi*Wlo, Alo*Whi ----
    #pragma unroll
    for (int pass = 0; pass < 3; pass++) {
        const uint32_t Abase = dbase + (pass == 2 ? SA_LO : SA_HI);
        const uint32_t Wbase = dbase + (pass == 1 ? SW_LO : SW_HI);
        #pragma unroll
        for (int kk = 0; kk < KH / 16; kk++) {
            const int k0 = kk * 16;
            uint32_t af[MI][4];
            #pragma unroll
            for (int mi = 0; mi < MI; mi++) {
                uint32_t addr = Abase
                    + (uint32_t)(warp_m + mi * 16 + a_row) * SPB
                    + (uint32_t)(k0 + a_k8) * 2;
                LDSM_X4(af[mi][0], af[mi][1], af[mi][2], af[mi][3], addr);
            }
            uint32_t bf[NI][2];
            #pragma unroll
            for (int nj = 0; nj < NI / 2; nj++) {
                uint32_t addr = Wbase
                    + (uint32_t)(warp_n + nj * 16 + b_row) * SPB
                    + (uint32_t)(k0 + b_k8) * 2;
                uint32_t r0, r1, r2, r3;
                LDSM_X4(r0, r1, r2, r3, addr);
                bf[nj*2+0][0] = r0; bf[nj*2+0][1] = r1;
                bf[nj*2+1][0] = r2; bf[nj*2+1][1] = r3;
            }
            #pragma unroll
            for (int mi = 0; mi < MI; mi++)
                #pragma unroll
                for (int ni = 0; ni < NI; ni++)
                    MMA_BF16(acc[mi][ni], af[mi], bf[ni]);
        }
    }

    // ---- dump u tile to SMEM, transposed [state][t], stride UST ----
    __syncthreads();
    float*  su    = (float*)dsm;
    float2* sexch = (float2*)(dsm + 256u * UST * 4);   // 2KB exchange
    #pragma unroll
    for (int mi = 0; mi < MI; mi++) {
        const int r = warp_m + mi * 16 + (lane >> 2);
        #pragma unroll
        for (int ni = 0; ni < NI; ni++) {
            const int c = warp_n + ni * 8 + (lane & 3) * 2;
            su[(size_t)c * UST + r]           = acc[mi][ni][0];
            su[(size_t)(c + 1) * UST + r]     = acc[mi][ni][1];
            su[(size_t)c * UST + r + 8]       = acc[mi][ni][2];
            su[(size_t)(c + 1) * UST + r + 8] = acc[mi][ni][3];
        }
    }
    __syncthreads();

    // ---- split local scan: 256 states x 2 time-halves, 64 steps each ----
    {
        const int n = tid & 255;
        const int j = tid >> 8;            // 0: t 0..63, 1: t 64..127
        const float4 cf = *(const float4*)&g_coef[n * 4];
        const int t0 = j * 64;
        float* yout = g_ys + (size_t)(row0 + t0) * STATE + n;
        const float* un = su + (size_t)n * UST + t0;
        float z = 0.0f, y = 0.0f;
        #pragma unroll 4
        for (int t = 0; t < 64; t++) {
            float u  = un[t];
            float zu = z + u;
            float zn = fmaf(cf.x, zu, cf.y * y);
            float yn = fmaf(cf.z, zu, cf.w * y);
            z = zn; y = yn;
            yout[(size_t)t * STATE] = y;
        }
        if (j == 0) {
            sexch[n] = make_float2(z, y);
            ((float2*)g_e1)[(size_t)blockIdx.x * STATE + n] = make_float2(z, y);
        }
        __syncthreads();
        if (j == 1) {
            float2 e1 = sexch[n];
            const float4 m6 = *(const float4*)&g_mp64[n * 4];
            float ze = fmaf(m6.x, e1.x, fmaf(m6.y, e1.y, z));
            float ye = fmaf(m6.z, e1.x, fmaf(m6.w, e1.y, y));
            ((float2*)g_carry)[(size_t)blockIdx.x * STATE + n] = make_float2(ze, ye);
        }
    }
}

// ---------------------------------------------------------------------------
// K2: scan across chunk end-states (M^128); rewrite carries to carry-INs.
// ---------------------------------------------------------------------------
__global__ void __launch_bounds__(256) scan_phase2_kernel()
{
    int n = threadIdx.x;
    int b = blockIdx.x;
    const float4 mp = *(const float4*)&g_mp[n * 4];

    float z = 0.0f, y = 0.0f;
    for (int c = 0; c < NCHUNK; c++) {
        size_t idx = ((size_t)b * NCHUNK + c) * STATE + n;
        float2 e = ((float2*)g_carry)[idx];
        ((float2*)g_carry)[idx] = make_float2(z, y);
        float zn = fmaf(mp.x, z, fmaf(mp.y, y, e.x));
        float yn = fmaf(mp.z, z, fmaf(mp.w, y, e.y));
        z = zn; y = yn;
    }
}

// ---------------------------------------------------------------------------
// K3: fix-up + GEMM2 (out = ys @ C^T + D*x, bf16x3). 512 threads, warps 4x4.
// Fix per K-half computed 4-way over time quarters:
//   t in [0,64):   fix = M^{t+1} s0
//   t in [64,128): fix = M^{t-63} (M^64 s0 + e1)
// added to the half-local y during A staging.
// ---------------------------------------------------------------------------
__global__ void __launch_bounds__(512, 1)
fix_gemm2_kernel(float* __restrict__ Cout,
                 const __nv_bfloat16* __restrict__ Whi,
                 const __nv_bfloat16* __restrict__ Wlo,
                 const float* __restrict__ xin,
                 const float* __restrict__ Dv)
{
    constexpr int N = 128, KFULL = 256;
    constexpr int MI = 2;              // 32/16
    constexpr int NI = 4;              // 32/8
    constexpr uint32_t SA_HI = 0;
    constexpr uint32_t SA_LO = 128u * SPB;
    constexpr uint32_t SW_HI = 2u * 128u * SPB;
    constexpr uint32_t SW_LO = SW_HI + (uint32_t)N * SPB;
    constexpr uint32_t SFIX  = SW_LO + (uint32_t)N * SPB;

    extern __shared__ char dsm_raw[];
    char* dsm = (char*)(((uintptr_t)dsm_raw + 1023) & ~(uintptr_t)1023);
    const uint32_t dbase = smem_u32(dsm);
    float* sfix = (float*)(dsm + SFIX);

    const int tid  = threadIdx.x;
    const int lane = tid & 31;
    const int w    = tid >> 5;
    const int row0 = blockIdx.x * 128;
    const int warp_m = (w & 3) * 32;
    const int warp_n = (w >> 2) * 32;

    const int a_row = (lane & 7) + ((lane >> 3) & 1) * 8;
    const int a_k8  = (lane >> 4) * 8;
    const int b_row = (lane & 7) + (lane >> 4) * 8;
    const int b_k8  = ((lane >> 3) & 1) * 8;

    float acc[MI][NI][4];
    #pragma unroll
    for (int mi = 0; mi < MI; mi++)
        #pragma unroll
        for (int ni = 0; ni < NI; ni++)
            #pragma unroll
            for (int q = 0; q < 4; q++)
                acc[mi][ni][q] = 0.0f;

    for (int h = 0; h < 2; h++) {
        const int kh0 = h * KH;
        __syncthreads();

        // ---- fix-up: 128 states x 4 time-quarters ----
        {
            const int nl = tid & 127;
            const int q  = tid >> 7;       // 0..3
            const int n  = kh0 + nl;
            const float2 s0 = ((float2*)g_carry)[(size_t)blockIdx.x * STATE + n];
            const float4 cf = *(const float4*)&g_coef[n * 4];
            float z, y;
            if (q == 0) { z = s0.x; y = s0.y; }
            else if (q == 1) {
                const float4 m3 = *(const float4*)&g_mp32[n * 4];
                z = fmaf(m3.x, s0.x, m3.y * s0.y);
                y = fmaf(m3.z, s0.x, m3.w * s0.y);
            } else {
                const float2 e1 = ((float2*)g_e1)[(size_t)blockIdx.x * STATE + n];
                const float4 m6 = *(const float4*)&g_mp64[n * 4];
                z = fmaf(m6.x, s0.x, fmaf(m6.y, s0.y, e1.x));
                y = fmaf(m6.z, s0.x, fmaf(m6.w, s0.y, e1.y));
                if (q == 3) {
                    const float4 m3 = *(const float4*)&g_mp32[n * 4];
                    float z3 = fmaf(m3.x, z, m3.y * y);
                    float y3 = fmaf(m3.z, z, m3.w * y);
                    z = z3; y = y3;
                }
            }
            float* fp = sfix + (size_t)(q * 32) * FST + nl;
            #pragma unroll 4
            for (int t = 0; t < 32; t++) {
                float zn = fmaf(cf.x, z, cf.y * y);
                float yn = fmaf(cf.z, z, cf.w * y);
                z = zn; y = yn;
                fp[(size_t)t * FST] = y;
            }
        }
        __syncthreads();

        // ---- stage A: y_loc + fix -> bf16 hi/lo ----
        #pragma unroll
        for (int it = 0; it < 8; it++) {
            int idx = tid + it * 512;
            int r   = idx >> 5;
            int k   = (idx & 31) * 4;
            float4 v = *(const float4*)(g_ys + (size_t)(row0 + r) * KFULL + kh0 + k);
            const float4 f = *(const float4*)(sfix + (size_t)r * FST + k);
            v.x += f.x; v.y += f.y; v.z += f.z; v.w += f.w;
            __nv_bfloat16 h0,l0,h1,l1,h2,l2,h3,l3;
            split2(v.x,h0,l0); split2(v.y,h1,l1); split2(v.z,h2,l2); split2(v.w,h3,l3);
            uint32_t o = (uint32_t)r * SPB + (uint32_t)k * 2;
            *(uint32_t*)(dsm + SA_HI + o)     = pack_bf16(h0, h1);
            *(uint32_t*)(dsm + SA_HI + o + 4) = pack_bf16(h2, h3);
            *(uint32_t*)(dsm + SA_LO + o)     = pack_bf16(l0, l1);
            *(uint32_t*)(dsm + SA_LO + o + 4) = pack_bf16(l2, l3);
        }
        // ---- stage W (C) hi/lo ----
        #pragma unroll
        for (int it = 0; it < 8; it++) {
            int idx  = tid + it * 512;         // 4096 uint4
            int half = idx >> 11;
            int rem  = idx & 2047;
            int r    = rem >> 4;
            int k8   = (rem & 15) * 8;
            const __nv_bfloat16* src = half ? Wlo : Whi;
            uint4 v = *(const uint4*)(src + (size_t)r * KFULL + kh0 + k8);
            uint32_t o = (half ? SW_LO : SW_HI) + (uint32_t)r * SPB + (uint32_t)k8 * 2;
            *(uint4*)(dsm + o) = v;
        }
        __syncthreads();

        // ---- 3 passes ----
        #pragma unroll
        for (int pass = 0; pass < 3; pass++) {
            const uint32_t Abase = dbase + (pass == 2 ? SA_LO : SA_HI);
            const uint32_t Wbase = dbase + (pass == 1 ? SW_LO : SW_HI);
            #pragma unroll
            for (int kk = 0; kk < KH / 16; kk++) {
                const int k0 = kk * 16;
                uint32_t af[MI][4];
                #pragma unroll
                for (int mi = 0; mi < MI; mi++) {
                    uint32_t addr = Abase
                        + (uint32_t)(warp_m + mi * 16 + a_row) * SPB
                        + (uint32_t)(k0 + a_k8) * 2;
                    LDSM_X4(af[mi][0], af[mi][1], af[mi][2], af[mi][3], addr);
                }
                uint32_t bf[NI][2];
                #pragma unroll
                for (int nj = 0; nj < NI / 2; nj++) {
                    uint32_t addr = Wbase
                        + (uint32_t)(warp_n + nj * 16 + b_row) * SPB
                        + (uint32_t)(k0 + b_k8) * 2;
                    uint32_t r0, r1, r2, r3;
                    LDSM_X4(r0, r1, r2, r3, addr);
                    bf[nj*2+0][0] = r0; bf[nj*2+0][1] = r1;
                    bf[nj*2+1][0] = r2; bf[nj*2+1][1] = r3;
                }
                #pragma unroll
                for (int mi = 0; mi < MI; mi++)
                    #pragma unroll
                    for (int ni = 0; ni < NI; ni++)
                        MMA_BF16(acc[mi][ni], af[mi], bf[ni]);
            }
        }
    }

    // ---- epilogue with D*x ----
    const int rbase = row0 + warp_m + (lane >> 2);
    const int cbase = warp_n + (lane & 3) * 2;
    #pragma unroll
    for (int ni = 0; ni < NI; ni++) {
        const int col = cbase + ni * 8;
        const float d0 = Dv[col], d1 = Dv[col + 1];
        #pragma unroll
        for (int mi = 0; mi < MI; mi++) {
            const int r0 = rbase + mi * 16;
            float* p0 = Cout + (size_t)r0 * N + col;
            float* p1 = Cout + (size_t)(r0 + 8) * N + col;
            const float2 x0 = *(const float2*)(xin + (size_t)r0 * N + col);
            const float2 x1 = *(const float2*)(xin + (size_t)(r0 + 8) * N + col);
            float2 o0 = make_float2(fmaf(d0, x0.x, acc[mi][ni][0]),
                                    fmaf(d1, x0.y, acc[mi][ni][1]));
            float2 o1 = make_float2(fmaf(d0, x1.x, acc[mi][ni][2]),
                                    fmaf(d1, x1.y, acc[mi][ni][3]));
            *(float2*)p0 = o0;
            *(float2*)p1 = o1;
        }
    }
}

// ---------------------------------------------------------------------------
// kernel_launch
// Inputs: x[16,4096,128], A_diag[256], steps[256], B[256,128], C[128,256], D[128]
// ---------------------------------------------------------------------------
extern "C" void kernel_launch(void* const* d_in, const int* in_sizes, int n_in,
                              void* d_out, int out_size)
{
    const float* x      = (const float*)d_in[0];
    const float* A_diag = (const float*)d_in[1];
    const float* steps  = (const float*)d_in[2];
    const float* Bw     = (const float*)d_in[3];
    const float* Cw     = (const float*)d_in[4];
    const float* Dv     = (const float*)d_in[5];
    float* out = (float*)d_out;

    __nv_bfloat16 *b1hi, *b1lo, *chi, *clo;
    cudaGetSymbolAddress((void**)&b1hi, g_B1hi);
    cudaGetSymbolAddress((void**)&b1lo, g_B1lo);
    cudaGetSymbolAddress((void**)&chi,  g_Chi);
    cudaGetSymbolAddress((void**)&clo,  g_Clo);

    const int smem1 = 1024 + 2 * 128 * SPB + 2 * 256 * SPB;                   // 209920
    const int smem3 = 1024 + 2 * 128 * SPB + 2 * 128 * SPB + 128 * FST * 4;   // 207872
    cudaFuncSetAttribute(gemm1_scan_kernel,
                         cudaFuncAttributeMaxDynamicSharedMemorySize, smem1);
    cudaFuncSetAttribute(fix_gemm2_kernel,
                         cudaFuncAttributeMaxDynamicSharedMemorySize, smem3);

    // 1. coefficients + weight bf16 split
    prep_kernel<<<1, 256>>>(A_diag, steps);
    wconv_kernel<<<(STATE * HIDDEN + HIDDEN * STATE) / 256, 256>>>(Bw, Cw);

    // 2. GEMM1 + split local scan
    gemm1_scan_kernel<<<NTILE, 512, smem1>>>(x, b1hi, b1lo);

    // 3. cross-chunk scan
    scan_phase2_kernel<<<BATCH, 256>>>();

    // 4. fix-up + GEMM2 (+ D*x)
    fix_gemm2_kernel<<<NTILE, 512, smem3>>>(out, chi, clo, x, Dv);
}

// round 6
// speedup vs baseline: 1.3333x; 1.2530x over previous
#include <cuda_runtime.h>
#include <cuda_fp16.h>
#include <math.h>
#include <stdint.h>

// Problem constants
#define HIDDEN 128
#define STATE  256
#define SEQ    4096
#define BATCH  16
#define TROWS  (BATCH * SEQ)      // 65536
#define LC     128                // scan chunk length == GEMM M-tile
#define NCHUNK (SEQ / LC)         // 32 chunks per sequence
#define NTILE  (TROWS / 128)      // 512 CTAs

// ---------------------------------------------------------------------------
// Scratch (static device globals — no allocations allowed)
// ---------------------------------------------------------------------------
__device__ float g_ys[(size_t)TROWS * STATE];   // piecewise-LOCAL scan y
__device__ float g_coef[STATE * 4];             // a,b,c,d  (M)
__device__ float g_mp32[STATE * 4];             // M^32
__device__ float g_mp64[STATE * 4];             // M^64
__device__ float g_mp  [STATE * 4];             // M^128
__device__ float g_step[STATE];
__device__ float g_carry[(size_t)NTILE * STATE * 2]; // per-chunk (z,y)
__device__ float g_e1   [(size_t)NTILE * STATE * 2]; // first-half local ends

// fp16 hi/lo split weights
__device__ __half g_B1hi[STATE * HIDDEN];  // step-scaled B
__device__ __half g_B1lo[STATE * HIDDEN];
__device__ __half g_Chi [HIDDEN * STATE];
__device__ __half g_Clo [HIDDEN * STATE];

// ---------------------------------------------------------------------------
// Helpers
// ---------------------------------------------------------------------------
__device__ __forceinline__ uint32_t smem_u32(const void* p) {
    uint32_t a;
    asm("{ .reg .u64 t; cvta.to.shared.u64 t, %1; cvt.u32.u64 %0, t; }"
        : "=r"(a) : "l"(p));
    return a;
}
__device__ __forceinline__ uint32_t pack_h(__half a, __half b) {
    return (uint32_t)__half_as_ushort(a) | ((uint32_t)__half_as_ushort(b) << 16);
}
__device__ __forceinline__ void split2h(float v, __half& h, __half& l) {
    h = __float2half(v);
    l = __float2half(v - __half2float(h));
}

#define LDSM_X4(r0, r1, r2, r3, addr)                                          \
    asm volatile("ldmatrix.sync.aligned.m8n8.x4.shared.b16 {%0,%1,%2,%3}, [%4];" \
        : "=r"(r0), "=r"(r1), "=r"(r2), "=r"(r3) : "r"(addr))

#define MMA_F16(d, a, b)                                                       \
    asm volatile("mma.sync.aligned.m16n8k16.row.col.f32.f16.f16.f32 "          \
        "{%0,%1,%2,%3}, {%4,%5,%6,%7}, {%8,%9}, {%0,%1,%2,%3};"                \
        : "+f"((d)[0]), "+f"((d)[1]), "+f"((d)[2]), "+f"((d)[3])               \
        : "r"((a)[0]), "r"((a)[1]), "r"((a)[2]), "r"((a)[3]),                  \
          "r"((b)[0]), "r"((b)[1]))

#define SPB 272          // padded SMEM row stride in bytes (136 fp16)
#define KH 128           // K chunk processed per staging pass
#define UST 129          // u-tile stride (floats), [state][t]
#define FST 132          // fix-tile stride (floats), [t][state_local]

// ---------------------------------------------------------------------------
// Prep: per-state coefficients, M^32 / M^64 / M^128 by squaring
// ---------------------------------------------------------------------------
__global__ void prep_kernel(const float* __restrict__ A_diag,
                            const float* __restrict__ steps)
{
    int n = threadIdx.x;
    float st   = 1.0f / (1.0f + expf(-steps[n]));
    float Av   = fmaxf(A_diag[n], 0.0f);
    float s2A  = st * st * Av;
    float schur = 1.0f / (1.0f + s2A);
    float a = 1.0f - s2A * schur;
    float b = -st * Av * schur;
    float c = st * schur;
    float d = schur;

    g_step[n] = st;
    g_coef[n*4+0] = a; g_coef[n*4+1] = b; g_coef[n*4+2] = c; g_coef[n*4+3] = d;

    float pa = a, pb = b, pc = c, pd = d;
    #pragma unroll
    for (int i = 0; i < 5; i++) {        // M^32
        float qa = pa*pa + pb*pc;
        float qb = pa*pb + pb*pd;
        float qc = pc*pa + pd*pc;
        float qd = pc*pb + pd*pd;
        pa = qa; pb = qb; pc = qc; pd = qd;
    }
    g_mp32[n*4+0] = pa; g_mp32[n*4+1] = pb; g_mp32[n*4+2] = pc; g_mp32[n*4+3] = pd;
    {                                     // M^64
        float qa = pa*pa + pb*pc;
        float qb = pa*pb + pb*pd;
        float qc = pc*pa + pd*pc;
        float qd = pc*pb + pd*pd;
        pa = qa; pb = qb; pc = qc; pd = qd;
    }
    g_mp64[n*4+0] = pa; g_mp64[n*4+1] = pb; g_mp64[n*4+2] = pc; g_mp64[n*4+3] = pd;
    {                                     // M^128
        float qa = pa*pa + pb*pc;
        float qb = pa*pb + pb*pd;
        float qc = pc*pa + pd*pc;
        float qd = pc*pb + pd*pd;
        pa = qa; pb = qb; pc = qc; pd = qd;
    }
    g_mp[n*4+0] = pa; g_mp[n*4+1] = pb; g_mp[n*4+2] = pc; g_mp[n*4+3] = pd;
}

// Weight conversion: step*B and C into fp16 hi/lo
__global__ void wconv_kernel(const float* __restrict__ Bw,
                             const float* __restrict__ Cw)
{
    int idx = blockIdx.x * 256 + threadIdx.x;
    if (idx < STATE * HIDDEN) {
        int n = idx >> 7;
        float v = g_step[n] * Bw[idx];
        __half h, l; split2h(v, h, l);
        g_B1hi[idx] = h; g_B1lo[idx] = l;
    } else {
        int j = idx - STATE * HIDDEN;
        __half h, l; split2h(Cw[j], h, l);
        g_Chi[j] = h; g_Clo[j] = l;
    }
}

// ---------------------------------------------------------------------------
// K1: GEMM1 (u = x @ (step*B)^T, fp16x2: Ah*Wh + Ah*Wl) fused with 2-way
// split local scan. 512 threads, warps 2x8 (warp tile 64x32).
// ---------------------------------------------------------------------------
__global__ void __launch_bounds__(512, 1)
gemm1_scan_kernel(const float* __restrict__ A,
                  const __half* __restrict__ Whi,
                  const __half* __restrict__ Wlo)
{
    constexpr int N = 256, KFULL = 128;
    constexpr int MI = 4;              // 64/16
    constexpr int NI = 4;              // 32/8
    constexpr uint32_t SA    = 0;
    constexpr uint32_t SW_HI = 128u * SPB;                    // 34816
    constexpr uint32_t SW_LO = SW_HI + (uint32_t)N * SPB;     // 104448

    extern __shared__ char dsm_raw[];
    char* dsm = (char*)(((uintptr_t)dsm_raw + 1023) & ~(uintptr_t)1023);
    const uint32_t dbase = smem_u32(dsm);

    const int tid  = threadIdx.x;
    const int lane = tid & 31;
    const int w    = tid >> 5;         // 0..15
    const int row0 = blockIdx.x * 128;
    const int warp_m = (w & 1) * 64;
    const int warp_n = (w >> 1) * 32;

    const int a_row = (lane & 7) + ((lane >> 3) & 1) * 8;
    const int a_k8  = (lane >> 4) * 8;
    const int b_row = (lane & 7) + (lane >> 4) * 8;
    const int b_k8  = ((lane >> 3) & 1) * 8;

    float acc[MI][NI][4];
    #pragma unroll
    for (int mi = 0; mi < MI; mi++)
        #pragma unroll
        for (int ni = 0; ni < NI; ni++)
            #pragma unroll
            for (int q = 0; q < 4; q++)
                acc[mi][ni][q] = 0.0f;

    // ---- stage A (x): fp32 -> fp16 hi only ----
    #pragma unroll
    for (int it = 0; it < 8; it++) {
        int idx = tid + it * 512;          // 4096 float4s
        int r   = idx >> 5;
        int k   = (idx & 31) * 4;
        float4 v = *(const float4*)(A + (size_t)(row0 + r) * KFULL + k);
        uint32_t o = (uint32_t)r * SPB + (uint32_t)k * 2;
        *(uint32_t*)(dsm + SA + o)     = pack_h(__float2half(v.x), __float2half(v.y));
        *(uint32_t*)(dsm + SA + o + 4) = pack_h(__float2half(v.z), __float2half(v.w));
    }
    // ---- stage W (step*B) hi/lo ----
    #pragma unroll
    for (int it = 0; it < 16; it++) {
        int idx  = tid + it * 512;         // 8192 uint4 (hi+lo)
        int half = idx >> 12;
        int rem  = idx & 4095;
        int r    = rem >> 4;
        int k8   = (rem & 15) * 8;
        const __half* src = half ? Wlo : Whi;
        uint4 v = *(const uint4*)(src + (size_t)r * KFULL + k8);
        uint32_t o = (half ? SW_LO : SW_HI) + (uint32_t)r * SPB + (uint32_t)k8 * 2;
        *(uint4*)(dsm + o) = v;
    }
    __syncthreads();

    // ---- 2 passes: A*Whi, A*Wlo ----
    #pragma unroll
    for (int pass = 0; pass < 2; pass++) {
        const uint32_t Abase = dbase + SA;
        const uint32_t Wbase = dbase + (pass ? SW_LO : SW_HI);
        #pragma unroll
        for (int kk = 0; kk < KH / 16; kk++) {
            const int k0 = kk * 16;
            uint32_t af[MI][4];
            #pragma unroll
            for (int mi = 0; mi < MI; mi++) {
                uint32_t addr = Abase
                    + (uint32_t)(warp_m + mi * 16 + a_row) * SPB
                    + (uint32_t)(k0 + a_k8) * 2;
                LDSM_X4(af[mi][0], af[mi][1], af[mi][2], af[mi][3], addr);
            }
            uint32_t bf[NI][2];
            #pragma unroll
            for (int nj = 0; nj < NI / 2; nj++) {
                uint32_t addr = Wbase
                    + (uint32_t)(warp_n + nj * 16 + b_row) * SPB
                    + (uint32_t)(k0 + b_k8) * 2;
                uint32_t r0, r1, r2, r3;
                LDSM_X4(r0, r1, r2, r3, addr);
                bf[nj*2+0][0] = r0; bf[nj*2+0][1] = r1;
                bf[nj*2+1][0] = r2; bf[nj*2+1][1] = r3;
            }
            #pragma unroll
            for (int mi = 0; mi < MI; mi++)
                #pragma unroll
                for (int ni = 0; ni < NI; ni++)
                    MMA_F16(acc[mi][ni], af[mi], bf[ni]);
        }
    }

    // ---- dump u tile to SMEM, transposed [state][t], stride UST ----
    __syncthreads();
    float*  su    = (float*)dsm;
    float2* sexch = (float2*)(dsm + 256u * UST * 4);   // 2KB exchange
    #pragma unroll
    for (int mi = 0; mi < MI; mi++) {
        const int r = warp_m + mi * 16 + (lane >> 2);
        #pragma unroll
        for (int ni = 0; ni < NI; ni++) {
            const int c = warp_n + ni * 8 + (lane & 3) * 2;
            su[(size_t)c * UST + r]           = acc[mi][ni][0];
            su[(size_t)(c + 1) * UST + r]     = acc[mi][ni][1];
            su[(size_t)c * UST + r + 8]       = acc[mi][ni][2];
            su[(size_t)(c + 1) * UST + r + 8] = acc[mi][ni][3];
        }
    }
    __syncthreads();

    // ---- split local scan: 256 states x 2 time-halves, 64 steps each ----
    {
        const int n = tid & 255;
        const int j = tid >> 8;            // 0: t 0..63, 1: t 64..127
        const float4 cf = *(const float4*)&g_coef[n * 4];
        const int t0 = j * 64;
        float* yout = g_ys + (size_t)(row0 + t0) * STATE + n;
        const float* un = su + (size_t)n * UST + t0;
        float z = 0.0f, y = 0.0f;
        #pragma unroll 4
        for (int t = 0; t < 64; t++) {
            float u  = un[t];
            float zu = z + u;
            float zn = fmaf(cf.x, zu, cf.y * y);
            float yn = fmaf(cf.z, zu, cf.w * y);
            z = zn; y = yn;
            yout[(size_t)t * STATE] = y;
        }
        if (j == 0) {
            sexch[n] = make_float2(z, y);
            ((float2*)g_e1)[(size_t)blockIdx.x * STATE + n] = make_float2(z, y);
        }
        __syncthreads();
        if (j == 1) {
            float2 e1 = sexch[n];
            const float4 m6 = *(const float4*)&g_mp64[n * 4];
            float ze = fmaf(m6.x, e1.x, fmaf(m6.y, e1.y, z));
            float ye = fmaf(m6.z, e1.x, fmaf(m6.w, e1.y, y));
            ((float2*)g_carry)[(size_t)blockIdx.x * STATE + n] = make_float2(ze, ye);
        }
    }
}

// ---------------------------------------------------------------------------
// K2: scan across chunk end-states (M^128); rewrite carries to carry-INs.
// ---------------------------------------------------------------------------
__global__ void __launch_bounds__(256) scan_phase2_kernel()
{
    int n = threadIdx.x;
    int b = blockIdx.x;
    const float4 mp = *(const float4*)&g_mp[n * 4];

    float z = 0.0f, y = 0.0f;
    for (int c = 0; c < NCHUNK; c++) {
        size_t idx = ((size_t)b * NCHUNK + c) * STATE + n;
        float2 e = ((float2*)g_carry)[idx];
        ((float2*)g_carry)[idx] = make_float2(z, y);
        float zn = fmaf(mp.x, z, fmaf(mp.y, y, e.x));
        float yn = fmaf(mp.z, z, fmaf(mp.w, y, e.y));
        z = zn; y = yn;
    }
}

// ---------------------------------------------------------------------------
// K3: fix-up + GEMM2 (out = ys @ C^T + D*x, fp16x2). 512 threads, warps 4x4.
// Fix per K-half computed 4-way over time quarters; added during A staging.
// ---------------------------------------------------------------------------
__global__ void __launch_bounds__(512, 1)
fix_gemm2_kernel(float* __restrict__ Cout,
                 const __half* __restrict__ Whi,
                 const __half* __restrict__ Wlo,
                 const float* __restrict__ xin,
                 const float* __restrict__ Dv)
{
    constexpr int N = 128, KFULL = 256;
    constexpr int MI = 2;              // 32/16
    constexpr int NI = 4;              // 32/8
    constexpr uint32_t SA    = 0;
    constexpr uint32_t SW_HI = 128u * SPB;                    // 34816
    constexpr uint32_t SW_LO = SW_HI + (uint32_t)N * SPB;     // 69632
    constexpr uint32_t SFIX  = SW_LO + (uint32_t)N * SPB;     // 104448

    extern __shared__ char dsm_raw[];
    char* dsm = (char*)(((uintptr_t)dsm_raw + 1023) & ~(uintptr_t)1023);
    const uint32_t dbase = smem_u32(dsm);
    float* sfix = (float*)(dsm + SFIX);

    const int tid  = threadIdx.x;
    const int lane = tid & 31;
    const int w    = tid >> 5;
    const int row0 = blockIdx.x * 128;
    const int warp_m = (w & 3) * 32;
    const int warp_n = (w >> 2) * 32;

    const int a_row = (lane & 7) + ((lane >> 3) & 1) * 8;
    const int a_k8  = (lane >> 4) * 8;
    const int b_row = (lane & 7) + (lane >> 4) * 8;
    const int b_k8  = ((lane >> 3) & 1) * 8;

    float acc[MI][NI][4];
    #pragma unroll
    for (int mi = 0; mi < MI; mi++)
        #pragma unroll
        for (int ni = 0; ni < NI; ni++)
            #pragma unroll
            for (int q = 0; q < 4; q++)
                acc[mi][ni][q] = 0.0f;

    for (int h = 0; h < 2; h++) {
        const int kh0 = h * KH;
        __syncthreads();

        // ---- fix-up: 128 states x 4 time-quarters ----
        {
            const int nl = tid & 127;
            const int q  = tid >> 7;       // 0..3
            const int n  = kh0 + nl;
            const float2 s0 = ((float2*)g_carry)[(size_t)blockIdx.x * STATE + n];
            const float4 cf = *(const float4*)&g_coef[n * 4];
            float z, y;
            if (q == 0) { z = s0.x; y = s0.y; }
            else if (q == 1) {
                const float4 m3 = *(const float4*)&g_mp32[n * 4];
                z = fmaf(m3.x, s0.x, m3.y * s0.y);
                y = fmaf(m3.z, s0.x, m3.w * s0.y);
            } else {
                const float2 e1 = ((float2*)g_e1)[(size_t)blockIdx.x * STATE + n];
                const float4 m6 = *(const float4*)&g_mp64[n * 4];
                z = fmaf(m6.x, s0.x, fmaf(m6.y, s0.y, e1.x));
                y = fmaf(m6.z, s0.x, fmaf(m6.w, s0.y, e1.y));
                if (q == 3) {
                    const float4 m3 = *(const float4*)&g_mp32[n * 4];
                    float z3 = fmaf(m3.x, z, m3.y * y);
                    float y3 = fmaf(m3.z, z, m3.w * y);
                    z = z3; y = y3;
                }
            }
            float* fp = sfix + (size_t)(q * 32) * FST + nl;
            #pragma unroll 4
            for (int t = 0; t < 32; t++) {
                float zn = fmaf(cf.x, z, cf.y * y);
                float yn = fmaf(cf.z, z, cf.w * y);
                z = zn; y = yn;
                fp[(size_t)t * FST] = y;
            }
        }
        __syncthreads();

        // ---- stage A: y_loc + fix -> fp16 hi only ----
        #pragma unroll
        for (int it = 0; it < 8; it++) {
            int idx = tid + it * 512;
            int r   = idx >> 5;
            int k   = (idx & 31) * 4;
            float4 v = *(const float4*)(g_ys + (size_t)(row0 + r) * KFULL + kh0 + k);
            const float4 f = *(const float4*)(sfix + (size_t)r * FST + k);
            v.x += f.x; v.y += f.y; v.z += f.z; v.w += f.w;
            uint32_t o = (uint32_t)r * SPB + (uint32_t)k * 2;
            *(uint32_t*)(dsm + SA + o)     = pack_h(__float2half(v.x), __float2half(v.y));
            *(uint32_t*)(dsm + SA + o + 4) = pack_h(__float2half(v.z), __float2half(v.w));
        }
        // ---- stage W (C) hi/lo ----
        #pragma unroll
        for (int it = 0; it < 8; it++) {
            int idx  = tid + it * 512;         // 4096 uint4
            int half = idx >> 11;
            int rem  = idx & 2047;
            int r    = rem >> 4;
            int k8   = (rem & 15) * 8;
            const __half* src = half ? Wlo : Whi;
            uint4 v = *(const uint4*)(src + (size_t)r * KFULL + kh0 + k8);
            uint32_t o = (half ? SW_LO : SW_HI) + (uint32_t)r * SPB + (uint32_t)k8 * 2;
            *(uint4*)(dsm + o) = v;
        }
        __syncthreads();

        // ---- 2 passes: A*Chi, A*Clo ----
        #pragma unroll
        for (int pass = 0; pass < 2; pass++) {
            const uint32_t Abase = dbase + SA;
            const uint32_t Wbase = dbase + (pass ? SW_LO : SW_HI);
            #pragma unroll
            for (int kk = 0; kk < KH / 16; kk++) {
                const int k0 = kk * 16;
                uint32_t af[MI][4];
                #pragma unroll
                for (int mi = 0; mi < MI; mi++) {
                    uint32_t addr = Abase
                        + (uint32_t)(warp_m + mi * 16 + a_row) * SPB
                        + (uint32_t)(k0 + a_k8) * 2;
                    LDSM_X4(af[mi][0], af[mi][1], af[mi][2], af[mi][3], addr);
                }
                uint32_t bf[NI][2];
                #pragma unroll
                for (int nj = 0; nj < NI / 2; nj++) {
                    uint32_t addr = Wbase
                        + (uint32_t)(warp_n + nj * 16 + b_row) * SPB
                        + (uint32_t)(k0 + b_k8) * 2;
                    uint32_t r0, r1, r2, r3;
                    LDSM_X4(r0, r1, r2, r3, addr);
                    bf[nj*2+0][0] = r0; bf[nj*2+0][1] = r1;
                    bf[nj*2+1][0] = r2; bf[nj*2+1][1] = r3;
                }
                #pragma unroll
                for (int mi = 0; mi < MI; mi++)
                    #pragma unroll
                    for (int ni = 0; ni < NI; ni++)
                        MMA_F16(acc[mi][ni], af[mi], bf[ni]);
            }
        }
    }

    // ---- epilogue with D*x ----
    const int rbase = row0 + warp_m + (lane >> 2);
    const int cbase = warp_n + (lane & 3) * 2;
    #pragma unroll
    for (int ni = 0; ni < NI; ni++) {
        const int col = cbase + ni * 8;
        const float d0 = Dv[col], d1 = Dv[col + 1];
        #pragma unroll
        for (int mi = 0; mi < MI; mi++) {
            const int r0 = rbase + mi * 16;
            float* p0 = Cout + (size_t)r0 * N + col;
            float* p1 = Cout + (size_t)(r0 + 8) * N + col;
            const float2 x0 = *(const float2*)(xin + (size_t)r0 * N + col);
            const float2 x1 = *(const float2*)(xin + (size_t)(r0 + 8) * N + col);
            float2 o0 = make_float2(fmaf(d0, x0.x, acc[mi][ni][0]),
                                    fmaf(d1, x0.y, acc[mi][ni][1]));
            float2 o1 = make_float2(fmaf(d0, x1.x, acc[mi][ni][2]),
                                    fmaf(d1, x1.y, acc[mi][ni][3]));
            *(float2*)p0 = o0;
            *(float2*)p1 = o1;
        }
    }
}

// ---------------------------------------------------------------------------
// kernel_launch
// Inputs: x[16,4096,128], A_diag[256], steps[256], B[256,128], C[128,256], D[128]
// ---------------------------------------------------------------------------
extern "C" void kernel_launch(void* const* d_in, const int* in_sizes, int n_in,
                              void* d_out, int out_size)
{
    const float* x      = (const float*)d_in[0];
    const float* A_diag = (const float*)d_in[1];
    const float* steps  = (const float*)d_in[2];
    const float* Bw     = (const float*)d_in[3];
    const float* Cw     = (const float*)d_in[4];
    const float* Dv     = (const float*)d_in[5];
    float* out = (float*)d_out;

    __half *b1hi, *b1lo, *chi, *clo;
    cudaGetSymbolAddress((void**)&b1hi, g_B1hi);
    cudaGetSymbolAddress((void**)&b1lo, g_B1lo);
    cudaGetSymbolAddress((void**)&chi,  g_Chi);
    cudaGetSymbolAddress((void**)&clo,  g_Clo);

    const int smem1 = 1024 + 128 * SPB + 2 * 256 * SPB;                       // 175104
    const int smem3 = 1024 + 128 * SPB + 2 * 128 * SPB + 128 * FST * 4;       // 173056
    cudaFuncSetAttribute(gemm1_scan_kernel,
                         cudaFuncAttributeMaxDynamicSharedMemorySize, smem1);
    cudaFuncSetAttribute(fix_gemm2_kernel,
                         cudaFuncAttributeMaxDynamicSharedMemorySize, smem3);

    // 1. coefficients + weight fp16 split
    prep_kernel<<<1, 256>>>(A_diag, steps);
    wconv_kernel<<<(STATE * HIDDEN + HIDDEN * STATE) / 256, 256>>>(Bw, Cw);

    // 2. GEMM1 + split local scan
    gemm1_scan_kernel<<<NTILE, 512, smem1>>>(x, b1hi, b1lo);

    // 3. cross-chunk scan
    scan_phase2_kernel<<<BATCH, 256>>>();

    // 4. fix-up + GEMM2 (+ D*x)
    fix_gemm2_kernel<<<NTILE, 512, smem3>>>(out, chi, clo, x, Dv);
}

// round 8
// speedup vs baseline: 1.9009x; 1.4258x over previous
#include <cuda_runtime.h>
#include <cuda_fp16.h>
#include <math.h>
#include <stdint.h>

// Problem constants
#define HIDDEN 128
#define STATE  256
#define SEQ    4096
#define BATCH  16
#define TROWS  (BATCH * SEQ)      // 65536
#define LC     128                // scan chunk length == GEMM M-tile
#define NCHUNK (SEQ / LC)         // 32 chunks per sequence
#define NTILE  (TROWS / 128)      // 512 CTAs

// ---------------------------------------------------------------------------
// Scratch (static device globals — no allocations allowed)
// ---------------------------------------------------------------------------
__device__ float g_ys[(size_t)TROWS * STATE];   // piecewise-LOCAL scan y
__device__ float g_coef[STATE * 4];             // a,b,c,d  (M)
__device__ float g_mp32[STATE * 4];             // M^32
__device__ float g_mp64[STATE * 4];             // M^64
__device__ float g_mp  [STATE * 4];             // M^128
__device__ float g_step[STATE];
__device__ float g_carry[(size_t)NTILE * STATE * 2]; // per-chunk (z,y)
__device__ float g_e1   [(size_t)NTILE * STATE * 2]; // first-half local ends

// fp16 weights
__device__ __half g_B1h[STATE * HIDDEN];   // step-scaled B
__device__ __half g_Ch [HIDDEN * STATE];

// ---------------------------------------------------------------------------
// Helpers
// ---------------------------------------------------------------------------
__device__ __forceinline__ uint32_t smem_u32(const void* p) {
    uint32_t a;
    asm("{ .reg .u64 t; cvta.to.shared.u64 t, %1; cvt.u32.u64 %0, t; }"
        : "=r"(a) : "l"(p));
    return a;
}
__device__ __forceinline__ uint32_t pack_h(__half a, __half b) {
    return (uint32_t)__half_as_ushort(a) | ((uint32_t)__half_as_ushort(b) << 16);
}

#define LDSM_X4(r0, r1, r2, r3, addr)                                          \
    asm volatile("ldmatrix.sync.aligned.m8n8.x4.shared.b16 {%0,%1,%2,%3}, [%4];" \
        : "=r"(r0), "=r"(r1), "=r"(r2), "=r"(r3) : "r"(addr))

#define MMA_F16(d, a, b)                                                       \
    asm volatile("mma.sync.aligned.m16n8k16.row.col.f32.f16.f16.f32 "          \
        "{%0,%1,%2,%3}, {%4,%5,%6,%7}, {%8,%9}, {%0,%1,%2,%3};"                \
        : "+f"((d)[0]), "+f"((d)[1]), "+f"((d)[2]), "+f"((d)[3])               \
        : "r"((a)[0]), "r"((a)[1]), "r"((a)[2]), "r"((a)[3]),                  \
          "r"((b)[0]), "r"((b)[1]))

#define SPB 272          // padded SMEM row stride in bytes (136 fp16)
#define KH 128           // K chunk processed per staging pass
#define UST 129          // u-tile stride (floats), [state][t]
#define FST 132          // fix-tile stride (floats), [t][state_local]

// ---------------------------------------------------------------------------
// Prep: per-state coefficients, M^32 / M^64 / M^128 by squaring
// ---------------------------------------------------------------------------
__global__ void prep_kernel(const float* __restrict__ A_diag,
                            const float* __restrict__ steps)
{
    int n = threadIdx.x;
    float st   = 1.0f / (1.0f + expf(-steps[n]));
    float Av   = fmaxf(A_diag[n], 0.0f);
    float s2A  = st * st * Av;
    float schur = 1.0f / (1.0f + s2A);
    float a = 1.0f - s2A * schur;
    float b = -st * Av * schur;
    float c = st * schur;
    float d = schur;

    g_step[n] = st;
    g_coef[n*4+0] = a; g_coef[n*4+1] = b; g_coef[n*4+2] = c; g_coef[n*4+3] = d;

    float pa = a, pb = b, pc = c, pd = d;
    #pragma unroll
    for (int i = 0; i < 5; i++) {        // M^32
        float qa = pa*pa + pb*pc;
        float qb = pa*pb + pb*pd;
        float qc = pc*pa + pd*pc;
        float qd = pc*pb + pd*pd;
        pa = qa; pb = qb; pc = qc; pd = qd;
    }
    g_mp32[n*4+0] = pa; g_mp32[n*4+1] = pb; g_mp32[n*4+2] = pc; g_mp32[n*4+3] = pd;
    {                                     // M^64
        float qa = pa*pa + pb*pc;
        float qb = pa*pb + pb*pd;
        float qc = pc*pa + pd*pc;
        float qd = pc*pb + pd*pd;
        pa = qa; pb = qb; pc = qc; pd = qd;
    }
    g_mp64[n*4+0] = pa; g_mp64[n*4+1] = pb; g_mp64[n*4+2] = pc; g_mp64[n*4+3] = pd;
    {                                     // M^128
        float qa = pa*pa + pb*pc;
        float qb = pa*pb + pb*pd;
        float qc = pc*pa + pd*pc;
        float qd = pc*pb + pd*pd;
        pa = qa; pb = qb; pc = qc; pd = qd;
    }
    g_mp[n*4+0] = pa; g_mp[n*4+1] = pb; g_mp[n*4+2] = pc; g_mp[n*4+3] = pd;
}

// Weight conversion: step*B and C into fp16
__global__ void wconv_kernel(const float* __restrict__ Bw,
                             const float* __restrict__ Cw)
{
    int idx = blockIdx.x * 256 + threadIdx.x;
    if (idx < STATE * HIDDEN) {
        int n = idx >> 7;
        g_B1h[idx] = __float2half(g_step[n] * Bw[idx]);
    } else {
        int j = idx - STATE * HIDDEN;
        g_Ch[j] = __float2half(Cw[j]);
    }
}

// ---------------------------------------------------------------------------
// K1: GEMM1 (u = x @ (step*B)^T, fp16 single pass) fused with 2-way split
// local scan. 512 threads, warps 2x8 (warp tile 64x32).
// SMEM is a union: staging phase uses A(128*SPB)+W(256*SPB)=104448 B;
// scan phase uses u-tile 256*UST*4=132096 B + 2KB exchange. Allocation
// must cover the MAX of both: 134144 B.
// ---------------------------------------------------------------------------
__global__ void __launch_bounds__(512, 1)
gemm1_scan_kernel(const float* __restrict__ A,
                  const __half* __restrict__ W)
{
    constexpr int N = 256, KFULL = 128;
    constexpr int MI = 4;              // 64/16
    constexpr int NI = 4;              // 32/8
    constexpr uint32_t SA = 0;
    constexpr uint32_t SW = 128u * SPB;                       // 34816

    extern __shared__ char dsm_raw[];
    char* dsm = (char*)(((uintptr_t)dsm_raw + 1023) & ~(uintptr_t)1023);
    const uint32_t dbase = smem_u32(dsm);

    const int tid  = threadIdx.x;
    const int lane = tid & 31;
    const int w    = tid >> 5;         // 0..15
    const int row0 = blockIdx.x * 128;
    const int warp_m = (w & 1) * 64;
    const int warp_n = (w >> 1) * 32;

    const int a_row = (lane & 7) + ((lane >> 3) & 1) * 8;
    const int a_k8  = (lane >> 4) * 8;
    const int b_row = (lane & 7) + (lane >> 4) * 8;
    const int b_k8  = ((lane >> 3) & 1) * 8;

    float acc[MI][NI][4];
    #pragma unroll
    for (int mi = 0; mi < MI; mi++)
        #pragma unroll
        for (int ni = 0; ni < NI; ni++)
            #pragma unroll
            for (int q = 0; q < 4; q++)
                acc[mi][ni][q] = 0.0f;

    // ---- stage A (x): fp32 -> fp16 ----
    #pragma unroll
    for (int it = 0; it < 8; it++) {
        int idx = tid + it * 512;          // 4096 float4s
        int r   = idx >> 5;
        int k   = (idx & 31) * 4;
        float4 v = *(const float4*)(A + (size_t)(row0 + r) * KFULL + k);
        uint32_t o = (uint32_t)r * SPB + (uint32_t)k * 2;
        *(uint32_t*)(dsm + SA + o)     = pack_h(__float2half(v.x), __float2half(v.y));
        *(uint32_t*)(dsm + SA + o + 4) = pack_h(__float2half(v.z), __float2half(v.w));
    }
    // ---- stage W (step*B) fp16 ----
    #pragma unroll
    for (int it = 0; it < 8; it++) {
        int idx = tid + it * 512;          // 4096 uint4
        int r   = idx >> 4;
        int k8  = (idx & 15) * 8;
        uint4 v = *(const uint4*)(W + (size_t)r * KFULL + k8);
        uint32_t o = SW + (uint32_t)r * SPB + (uint32_t)k8 * 2;
        *(uint4*)(dsm + o) = v;
    }
    __syncthreads();

    // ---- single fp16 pass ----
    {
        const uint32_t Abase = dbase + SA;
        const uint32_t Wbase = dbase + SW;
        #pragma unroll
        for (int kk = 0; kk < KH / 16; kk++) {
            const int k0 = kk * 16;
            uint32_t af[MI][4];
            #pragma unroll
            for (int mi = 0; mi < MI; mi++) {
                uint32_t addr = Abase
                    + (uint32_t)(warp_m + mi * 16 + a_row) * SPB
                    + (uint32_t)(k0 + a_k8) * 2;
                LDSM_X4(af[mi][0], af[mi][1], af[mi][2], af[mi][3], addr);
            }
            uint32_t bf[NI][2];
            #pragma unroll
            for (int nj = 0; nj < NI / 2; nj++) {
                uint32_t addr = Wbase
                    + (uint32_t)(warp_n + nj * 16 + b_row) * SPB
                    + (uint32_t)(k0 + b_k8) * 2;
                uint32_t r0, r1, r2, r3;
                LDSM_X4(r0, r1, r2, r3, addr);
                bf[nj*2+0][0] = r0; bf[nj*2+0][1] = r1;
                bf[nj*2+1][0] = r2; bf[nj*2+1][1] = r3;
            }
            #pragma unroll
            for (int mi = 0; mi < MI; mi++)
                #pragma unroll
                for (int ni = 0; ni < NI; ni++)
                    MMA_F16(acc[mi][ni], af[mi], bf[ni]);
        }
    }

    // ---- dump u tile to SMEM, transposed [state][t], stride UST ----
    __syncthreads();
    float*  su    = (float*)dsm;
    float2* sexch = (float2*)(dsm + 256u * UST * 4);   // 2KB exchange
    #pragma unroll
    for (int mi = 0; mi < MI; mi++) {
        const int r = warp_m + mi * 16 + (lane >> 2);
        #pragma unroll
        for (int ni = 0; ni < NI; ni++) {
            const int c = warp_n + ni * 8 + (lane & 3) * 2;
            su[(size_t)c * UST + r]           = acc[mi][ni][0];
            su[(size_t)(c + 1) * UST + r]     = acc[mi][ni][1];
            su[(size_t)c * UST + r + 8]       = acc[mi][ni][2];
            su[(size_t)(c + 1) * UST + r + 8] = acc[mi][ni][3];
        }
    }
    __syncthreads();

    // ---- split local scan: 256 states x 2 time-halves, 64 steps each ----
    {
        const int n = tid & 255;
        const int j = tid >> 8;            // 0: t 0..63, 1: t 64..127
        const float4 cf = *(const float4*)&g_coef[n * 4];
        const int t0 = j * 64;
        float* yout = g_ys + (size_t)(row0 + t0) * STATE + n;
        const float* un = su + (size_t)n * UST + t0;
        float z = 0.0f, y = 0.0f;
        #pragma unroll 4
        for (int t = 0; t < 64; t++) {
            float u  = un[t];
            float zu = z + u;
            float zn = fmaf(cf.x, zu, cf.y * y);
            float yn = fmaf(cf.z, zu, cf.w * y);
            z = zn; y = yn;
            yout[(size_t)t * STATE] = y;
        }
        if (j == 0) {
            sexch[n] = make_float2(z, y);
            ((float2*)g_e1)[(size_t)blockIdx.x * STATE + n] = make_float2(z, y);
        }
        __syncthreads();
        if (j == 1) {
            float2 e1 = sexch[n];
            const float4 m6 = *(const float4*)&g_mp64[n * 4];
            float ze = fmaf(m6.x, e1.x, fmaf(m6.y, e1.y, z));
            float ye = fmaf(m6.z, e1.x, fmaf(m6.w, e1.y, y));
            ((float2*)g_carry)[(size_t)blockIdx.x * STATE + n] = make_float2(ze, ye);
        }
    }
}

// ---------------------------------------------------------------------------
// K2: scan across chunk end-states (M^128). Prefetch all 32 carries first
// (MLP=32), then serial combine, then write carry-INs.
// ---------------------------------------------------------------------------
__global__ void __launch_bounds__(256) scan_phase2_kernel()
{
    int n = threadIdx.x;
    int b = blockIdx.x;
    const float4 mp = *(const float4*)&g_mp[n * 4];

    float2 e[NCHUNK];
    #pragma unroll
    for (int c = 0; c < NCHUNK; c++)
        e[c] = ((float2*)g_carry)[((size_t)b * NCHUNK + c) * STATE + n];

    float z = 0.0f, y = 0.0f;
    #pragma unroll
    for (int c = 0; c < NCHUNK; c++) {
        ((float2*)g_carry)[((size_t)b * NCHUNK + c) * STATE + n] = make_float2(z, y);
        float zn = fmaf(mp.x, z, fmaf(mp.y, y, e[c].x));
        float yn = fmaf(mp.z, z, fmaf(mp.w, y, e[c].y));
        z = zn; y = yn;
    }
}

// ---------------------------------------------------------------------------
// K3: fix-up + GEMM2 (out = ys @ C^T + D*x, fp16 single pass). 512 threads,
// warps 4x4. Fix per K-half computed 4-way over time quarters.
// ---------------------------------------------------------------------------
__global__ void __launch_bounds__(512, 1)
fix_gemm2_kernel(float* __restrict__ Cout,
                 const __half* __restrict__ W,
                 const float* __restrict__ xin,
                 const float* __restrict__ Dv)
{
    constexpr int N = 128, KFULL = 256;
    constexpr int MI = 2;              // 32/16
    constexpr int NI = 4;              // 32/8
    constexpr uint32_t SA   = 0;
    constexpr uint32_t SW   = 128u * SPB;                     // 34816
    constexpr uint32_t SFIX = SW + (uint32_t)N * SPB;         // 69632

    extern __shared__ char dsm_raw[];
    char* dsm = (char*)(((uintptr_t)dsm_raw + 1023) & ~(uintptr_t)1023);
    const uint32_t dbase = smem_u32(dsm);
    float* sfix = (float*)(dsm + SFIX);

    const int tid  = threadIdx.x;
    const int lane = tid & 31;
    const int w    = tid >> 5;
    const int row0 = blockIdx.x * 128;
    const int warp_m = (w & 3) * 32;
    const int warp_n = (w >> 2) * 32;

    const int a_row = (lane & 7) + ((lane >> 3) & 1) * 8;
    const int a_k8  = (lane >> 4) * 8;
    const int b_row = (lane & 7) + (lane >> 4) * 8;
    const int b_k8  = ((lane >> 3) & 1) * 8;

    float acc[MI][NI][4];
    #pragma unroll
    for (int mi = 0; mi < MI; mi++)
        #pragma unroll
        for (int ni = 0; ni < NI; ni++)
            #pragma unroll
            for (int q = 0; q < 4; q++)
                acc[mi][ni][q] = 0.0f;

    for (int h = 0; h < 2; h++) {
        const int kh0 = h * KH;
        __syncthreads();

        // ---- fix-up: 128 states x 4 time-quarters ----
        {
            const int nl = tid & 127;
            const int q  = tid >> 7;       // 0..3
            const int n  = kh0 + nl;
            const float2 s0 = ((float2*)g_carry)[(size_t)blockIdx.x * STATE + n];
            const float4 cf = *(const float4*)&g_coef[n * 4];
            float z, y;
            if (q == 0) { z = s0.x; y = s0.y; }
            else if (q == 1) {
                const float4 m3 = *(const float4*)&g_mp32[n * 4];
                z = fmaf(m3.x, s0.x, m3.y * s0.y);
                y = fmaf(m3.z, s0.x, m3.w * s0.y);
            } else {
                const float2 e1 = ((float2*)g_e1)[(size_t)blockIdx.x * STATE + n];
                const float4 m6 = *(const float4*)&g_mp64[n * 4];
                z = fmaf(m6.x, s0.x, fmaf(m6.y, s0.y, e1.x));
                y = fmaf(m6.z, s0.x, fmaf(m6.w, s0.y, e1.y));
                if (q == 3) {
                    const float4 m3 = *(const float4*)&g_mp32[n * 4];
                    float z3 = fmaf(m3.x, z, m3.y * y);
                    float y3 = fmaf(m3.z, z, m3.w * y);
                    z = z3; y = y3;
                }
            }
            float* fp = sfix + (size_t)(q * 32) * FST + nl;
            #pragma unroll 4
            for (int t = 0; t < 32; t++) {
                float zn = fmaf(cf.x, z, cf.y * y);
                float yn = fmaf(cf.z, z, cf.w * y);
                z = zn; y = yn;
                fp[(size_t)t * FST] = y;
            }
        }
        __syncthreads();

        // ---- stage A: y_loc + fix -> fp16 ----
        #pragma unroll
        for (int it = 0; it < 8; it++) {
            int idx = tid + it * 512;
            int r   = idx >> 5;
            int k   = (idx & 31) * 4;
            float4 v = *(const float4*)(g_ys + (size_t)(row0 + r) * KFULL + kh0 + k);
            const float4 f = *(const float4*)(sfix + (size_t)r * FST + k);
            v.x += f.x; v.y += f.y; v.z += f.z; v.w += f.w;
            uint32_t o = (uint32_t)r * SPB + (uint32_t)k * 2;
            *(uint32_t*)(dsm + SA + o)     = pack_h(__float2half(v.x), __float2half(v.y));
            *(uint32_t*)(dsm + SA + o + 4) = pack_h(__float2half(v.z), __float2half(v.w));
        }
        // ---- stage W (C) fp16 ----
        #pragma unroll
        for (int it = 0; it < 4; it++) {
            int idx = tid + it * 512;          // 2048 uint4
            int r   = idx >> 4;
            int k8  = (idx & 15) * 8;
            uint4 v = *(const uint4*)(W + (size_t)r * KFULL + kh0 + k8);
            uint32_t o = SW + (uint32_t)r * SPB + (uint32_t)k8 * 2;
            *(uint4*)(dsm + o) = v;
        }
        __syncthreads();

        // ---- single fp16 pass ----
        {
            const uint32_t Abase = dbase + SA;
            const uint32_t Wbase = dbase + SW;
            #pragma unroll
            for (int kk = 0; kk < KH / 16; kk++) {
                const int k0 = kk * 16;
                uint32_t af[MI][4];
                #pragma unroll
                for (int mi = 0; mi < MI; mi++) {
                    uint32_t addr = Abase
                        + (uint32_t)(warp_m + mi * 16 + a_row) * SPB
                        + (uint32_t)(k0 + a_k8) * 2;
                    LDSM_X4(af[mi][0], af[mi][1], af[mi][2], af[mi][3], addr);
                }
                uint32_t bf[NI][2];
                #pragma unroll
                for (int nj = 0; nj < NI / 2; nj++) {
                    uint32_t addr = Wbase
                        + (uint32_t)(warp_n + nj * 16 + b_row) * SPB
                        + (uint32_t)(k0 + b_k8) * 2;
                    uint32_t r0, r1, r2, r3;
                    LDSM_X4(r0, r1, r2, r3, addr);
                    bf[nj*2+0][0] = r0; bf[nj*2+0][1] = r1;
                    bf[nj*2+1][0] = r2; bf[nj*2+1][1] = r3;
                }
                #pragma unroll
                for (int mi = 0; mi < MI; mi++)
                    #pragma unroll
                    for (int ni = 0; ni < NI; ni++)
                        MMA_F16(acc[mi][ni], af[mi], bf[ni]);
            }
        }
    }

    // ---- epilogue with D*x ----
    const int rbase = row0 + warp_m + (lane >> 2);
    const int cbase = warp_n + (lane & 3) * 2;
    #pragma unroll
    for (int ni = 0; ni < NI; ni++) {
        const int col = cbase + ni * 8;
        const float d0 = Dv[col], d1 = Dv[col + 1];
        #pragma unroll
        for (int mi = 0; mi < MI; mi++) {
            const int r0 = rbase + mi * 16;
            float* p0 = Cout + (size_t)r0 * N + col;
            float* p1 = Cout + (size_t)(r0 + 8) * N + col;
            const float2 x0 = *(const float2*)(xin + (size_t)r0 * N + col);
            const float2 x1 = *(const float2*)(xin + (size_t)(r0 + 8) * N + col);
            float2 o0 = make_float2(fmaf(d0, x0.x, acc[mi][ni][0]),
                                    fmaf(d1, x0.y, acc[mi][ni][1]));
            float2 o1 = make_float2(fmaf(d0, x1.x, acc[mi][ni][2]),
                                    fmaf(d1, x1.y, acc[mi][ni][3]));
            *(float2*)p0 = o0;
            *(float2*)p1 = o1;
        }
    }
}

// ---------------------------------------------------------------------------
// kernel_launch
// Inputs: x[16,4096,128], A_diag[256], steps[256], B[256,128], C[128,256], D[128]
// ---------------------------------------------------------------------------
extern "C" void kernel_launch(void* const* d_in, const int* in_sizes, int n_in,
                              void* d_out, int out_size)
{
    const float* x      = (const float*)d_in[0];
    const float* A_diag = (const float*)d_in[1];
    const float* steps  = (const float*)d_in[2];
    const float* Bw     = (const float*)d_in[3];
    const float* Cw     = (const float*)d_in[4];
    const float* Dv     = (const float*)d_in[5];
    float* out = (float*)d_out;

    __half *b1h, *ch;
    cudaGetSymbolAddress((void**)&b1h, g_B1h);
    cudaGetSymbolAddress((void**)&ch,  g_Ch);

    // K1 SMEM must cover BOTH phases:
    //   staging: 128*SPB + 256*SPB              = 104448
    //   scan:    256*UST*4 (132096) + 2048 exch = 134144   <- max
    const int smem1 = 1024 + 256 * UST * 4 + 2048;                        // 135168
    const int smem3 = 1024 + 128 * SPB + 128 * SPB + 128 * FST * 4;       // 138240
    cudaFuncSetAttribute(gemm1_scan_kernel,
                         cudaFuncAttributeMaxDynamicSharedMemorySize, smem1);
    cudaFuncSetAttribute(fix_gemm2_kernel,
                         cudaFuncAttributeMaxDynamicSharedMemorySize, smem3);

    // 1. coefficients + weight fp16 conversion
    prep_kernel<<<1, 256>>>(A_diag, steps);
    wconv_kernel<<<(STATE * HIDDEN + HIDDEN * STATE) / 256, 256>>>(Bw, Cw);

    // 2. GEMM1 + split local scan
    gemm1_scan_kernel<<<NTILE, 512, smem1>>>(x, b1h);

    // 3. cross-chunk scan
    scan_phase2_kernel<<<BATCH, 256>>>();

    // 4. fix-up + GEMM2 (+ D*x)
    fix_gemm2_kernel<<<NTILE, 512, smem3>>>(out, ch, x, Dv);
}

// round 9
// speedup vs baseline: 2.4424x; 1.2849x over previous
#include <cuda_runtime.h>
#include <cuda_fp16.h>
#include <math.h>
#include <stdint.h>

// Problem constants
#define HIDDEN 128
#define STATE  256
#define SEQ    4096
#define BATCH  16
#define TROWS  (BATCH * SEQ)      // 65536
#define LC     128                // scan chunk length == GEMM M-tile
#define NCHUNK (SEQ / LC)         // 32 chunks per sequence
#define NTILE  (TROWS / 128)      // 512 CTAs

// ---------------------------------------------------------------------------
// Scratch (static device globals — no allocations allowed)
// ---------------------------------------------------------------------------
__device__ __half g_ysh[(size_t)TROWS * STATE]; // piecewise-LOCAL scan y (fp16)
__device__ float g_coef[STATE * 4];             // a,b,c,d  (M)
__device__ float g_mp32[STATE * 4];             // M^32
__device__ float g_mp64[STATE * 4];             // M^64
__device__ float g_mp  [STATE * 4];             // M^128
__device__ float g_carry[(size_t)NTILE * STATE * 2]; // per-chunk (z,y)
__device__ float g_e1   [(size_t)NTILE * STATE * 2]; // first-half local ends

// fp16 weights
__device__ __half g_B1h[STATE * HIDDEN];   // step-scaled B
__device__ __half g_Ch [HIDDEN * STATE];

// ---------------------------------------------------------------------------
// Helpers
// ---------------------------------------------------------------------------
__device__ __forceinline__ uint32_t smem_u32(const void* p) {
    uint32_t a;
    asm("{ .reg .u64 t; cvta.to.shared.u64 t, %1; cvt.u32.u64 %0, t; }"
        : "=r"(a) : "l"(p));
    return a;
}
__device__ __forceinline__ uint32_t pack_h(__half a, __half b) {
    return (uint32_t)__half_as_ushort(a) | ((uint32_t)__half_as_ushort(b) << 16);
}

#define LDSM_X4(r0, r1, r2, r3, addr)                                          \
    asm volatile("ldmatrix.sync.aligned.m8n8.x4.shared.b16 {%0,%1,%2,%3}, [%4];" \
        : "=r"(r0), "=r"(r1), "=r"(r2), "=r"(r3) : "r"(addr))

#define MMA_F16(d, a, b)                                                       \
    asm volatile("mma.sync.aligned.m16n8k16.row.col.f32.f16.f16.f32 "          \
        "{%0,%1,%2,%3}, {%4,%5,%6,%7}, {%8,%9}, {%0,%1,%2,%3};"                \
        : "+f"((d)[0]), "+f"((d)[1]), "+f"((d)[2]), "+f"((d)[3])               \
        : "r"((a)[0]), "r"((a)[1]), "r"((a)[2]), "r"((a)[3]),                  \
          "r"((b)[0]), "r"((b)[1]))

#define SPB 272          // padded SMEM row stride in bytes (136 fp16)
#define KH 128           // K chunk processed per staging pass
#define UST 129          // u-tile stride (floats), [state][t]
#define FST 132          // fix-tile stride (floats), [t][state_local]

// ---------------------------------------------------------------------------
// Combined prep + weight conversion (one launch).
// Block 0: per-state coefficients + M^32/M^64/M^128.
// Blocks 1..384: convert step*B and C to fp16 (sigmoid inlined — no
// dependency on block 0).
// ---------------------------------------------------------------------------
__global__ void prep_wconv_kernel(const float* __restrict__ A_diag,
                                  const float* __restrict__ steps,
                                  const float* __restrict__ Bw,
                                  const float* __restrict__ Cw)
{
    if (blockIdx.x == 0) {
        int n = threadIdx.x;
        float st   = 1.0f / (1.0f + expf(-steps[n]));
        float Av   = fmaxf(A_diag[n], 0.0f);
        float s2A  = st * st * Av;
        float schur = 1.0f / (1.0f + s2A);
        float a = 1.0f - s2A * schur;
        float b = -st * Av * schur;
        float c = st * schur;
        float d = schur;

        g_coef[n*4+0] = a; g_coef[n*4+1] = b; g_coef[n*4+2] = c; g_coef[n*4+3] = d;

        float pa = a, pb = b, pc = c, pd = d;
        #pragma unroll
        for (int i = 0; i < 5; i++) {        // M^32
            float qa = pa*pa + pb*pc;
            float qb = pa*pb + pb*pd;
            float qc = pc*pa + pd*pc;
            float qd = pc*pb + pd*pd;
            pa = qa; pb = qb; pc = qc; pd = qd;
        }
        g_mp32[n*4+0] = pa; g_mp32[n*4+1] = pb; g_mp32[n*4+2] = pc; g_mp32[n*4+3] = pd;
        {                                     // M^64
            float qa = pa*pa + pb*pc;
            float qb = pa*pb + pb*pd;
            float qc = pc*pa + pd*pc;
            float qd = pc*pb + pd*pd;
            pa = qa; pb = qb; pc = qc; pd = qd;
        }
        g_mp64[n*4+0] = pa; g_mp64[n*4+1] = pb; g_mp64[n*4+2] = pc; g_mp64[n*4+3] = pd;
        {                                     // M^128
            float qa = pa*pa + pb*pc;
            float qb = pa*pb + pb*pd;
            float qc = pc*pa + pd*pc;
            float qd = pc*pb + pd*pd;
            pa = qa; pb = qb; pc = qc; pd = qd;
        }
        g_mp[n*4+0] = pa; g_mp[n*4+1] = pb; g_mp[n*4+2] = pc; g_mp[n*4+3] = pd;
    } else {
        int idx = (blockIdx.x - 1) * 256 + threadIdx.x;
        if (idx < STATE * HIDDEN) {
            int n = idx >> 7;
            float st = 1.0f / (1.0f + expf(-steps[n]));
            g_B1h[idx] = __float2half(st * Bw[idx]);
        } else {
            int j = idx - STATE * HIDDEN;
            g_Ch[j] = __float2half(Cw[j]);
        }
    }
}

// ---------------------------------------------------------------------------
// K1: GEMM1 (u = x @ (step*B)^T, fp16 single pass) fused with 2-way split
// local scan. 512 threads, warps 2x8 (warp tile 64x32). y_loc stored fp16.
// SMEM union: staging 104448 B; scan tile 132096 + 2048 exch = 134144 (max).
// ---------------------------------------------------------------------------
__global__ void __launch_bounds__(512, 1)
gemm1_scan_kernel(const float* __restrict__ A,
                  const __half* __restrict__ W)
{
    constexpr int N = 256, KFULL = 128;
    constexpr int MI = 4;              // 64/16
    constexpr int NI = 4;              // 32/8
    constexpr uint32_t SA = 0;
    constexpr uint32_t SW = 128u * SPB;                       // 34816

    extern __shared__ char dsm_raw[];
    char* dsm = (char*)(((uintptr_t)dsm_raw + 1023) & ~(uintptr_t)1023);
    const uint32_t dbase = smem_u32(dsm);

    const int tid  = threadIdx.x;
    const int lane = tid & 31;
    const int w    = tid >> 5;         // 0..15
    const int row0 = blockIdx.x * 128;
    const int warp_m = (w & 1) * 64;
    const int warp_n = (w >> 1) * 32;

    const int a_row = (lane & 7) + ((lane >> 3) & 1) * 8;
    const int a_k8  = (lane >> 4) * 8;
    const int b_row = (lane & 7) + (lane >> 4) * 8;
    const int b_k8  = ((lane >> 3) & 1) * 8;

    float acc[MI][NI][4];
    #pragma unroll
    for (int mi = 0; mi < MI; mi++)
        #pragma unroll
        for (int ni = 0; ni < NI; ni++)
            #pragma unroll
            for (int q = 0; q < 4; q++)
                acc[mi][ni][q] = 0.0f;

    // ---- stage A (x): fp32 -> fp16 ----
    #pragma unroll
    for (int it = 0; it < 8; it++) {
        int idx = tid + it * 512;          // 4096 float4s
        int r   = idx >> 5;
        int k   = (idx & 31) * 4;
        float4 v = *(const float4*)(A + (size_t)(row0 + r) * KFULL + k);
        uint32_t o = (uint32_t)r * SPB + (uint32_t)k * 2;
        *(uint32_t*)(dsm + SA + o)     = pack_h(__float2half(v.x), __float2half(v.y));
        *(uint32_t*)(dsm + SA + o + 4) = pack_h(__float2half(v.z), __float2half(v.w));
    }
    // ---- stage W (step*B) fp16 ----
    #pragma unroll
    for (int it = 0; it < 8; it++) {
        int idx = tid + it * 512;          // 4096 uint4
        int r   = idx >> 4;
        int k8  = (idx & 15) * 8;
        uint4 v = *(const uint4*)(W + (size_t)r * KFULL + k8);
        uint32_t o = SW + (uint32_t)r * SPB + (uint32_t)k8 * 2;
        *(uint4*)(dsm + o) = v;
    }
    __syncthreads();

    // ---- single fp16 pass ----
    {
        const uint32_t Abase = dbase + SA;
        const uint32_t Wbase = dbase + SW;
        #pragma unroll
        for (int kk = 0; kk < KH / 16; kk++) {
            const int k0 = kk * 16;
            uint32_t af[MI][4];
            #pragma unroll
            for (int mi = 0; mi < MI; mi++) {
                uint32_t addr = Abase
                    + (uint32_t)(warp_m + mi * 16 + a_row) * SPB
                    + (uint32_t)(k0 + a_k8) * 2;
                LDSM_X4(af[mi][0], af[mi][1], af[mi][2], af[mi][3], addr);
            }
            uint32_t bf[NI][2];
            #pragma unroll
            for (int nj = 0; nj < NI / 2; nj++) {
                uint32_t addr = Wbase
                    + (uint32_t)(warp_n + nj * 16 + b_row) * SPB
                    + (uint32_t)(k0 + b_k8) * 2;
                uint32_t r0, r1, r2, r3;
                LDSM_X4(r0, r1, r2, r3, addr);
                bf[nj*2+0][0] = r0; bf[nj*2+0][1] = r1;
                bf[nj*2+1][0] = r2; bf[nj*2+1][1] = r3;
            }
            #pragma unroll
            for (int mi = 0; mi < MI; mi++)
                #pragma unroll
                for (int ni = 0; ni < NI; ni++)
                    MMA_F16(acc[mi][ni], af[mi], bf[ni]);
        }
    }

    // ---- dump u tile to SMEM, transposed [state][t], stride UST ----
    __syncthreads();
    float*  su    = (float*)dsm;
    float2* sexch = (float2*)(dsm + 256u * UST * 4);   // 2KB exchange
    #pragma unroll
    for (int mi = 0; mi < MI; mi++) {
        const int r = warp_m + mi * 16 + (lane >> 2);
        #pragma unroll
        for (int ni = 0; ni < NI; ni++) {
            const int c = warp_n + ni * 8 + (lane & 3) * 2;
            su[(size_t)c * UST + r]           = acc[mi][ni][0];
            su[(size_t)(c + 1) * UST + r]     = acc[mi][ni][1];
            su[(size_t)c * UST + r + 8]       = acc[mi][ni][2];
            su[(size_t)(c + 1) * UST + r + 8] = acc[mi][ni][3];
        }
    }
    __syncthreads();

    // ---- split local scan: 256 states x 2 time-halves, 64 steps each ----
    {
        const int n = tid & 255;
        const int j = tid >> 8;            // 0: t 0..63, 1: t 64..127
        const float4 cf = *(const float4*)&g_coef[n * 4];
        const int t0 = j * 64;
        __half* yout = g_ysh + (size_t)(row0 + t0) * STATE + n;
        const float* un = su + (size_t)n * UST + t0;
        float z = 0.0f, y = 0.0f;
        #pragma unroll 4
        for (int t = 0; t < 64; t++) {
            float u  = un[t];
            float zu = z + u;
            float zn = fmaf(cf.x, zu, cf.y * y);
            float yn = fmaf(cf.z, zu, cf.w * y);
            z = zn; y = yn;
            yout[(size_t)t * STATE] = __float2half(y);
        }
        if (j == 0) {
            sexch[n] = make_float2(z, y);
            ((float2*)g_e1)[(size_t)blockIdx.x * STATE + n] = make_float2(z, y);
        }
        __syncthreads();
        if (j == 1) {
            float2 e1 = sexch[n];
            const float4 m6 = *(const float4*)&g_mp64[n * 4];
            float ze = fmaf(m6.x, e1.x, fmaf(m6.y, e1.y, z));
            float ye = fmaf(m6.z, e1.x, fmaf(m6.w, e1.y, y));
            ((float2*)g_carry)[(size_t)blockIdx.x * STATE + n] = make_float2(ze, ye);
        }
    }
}

// ---------------------------------------------------------------------------
// K2: scan across chunk end-states (M^128). Prefetch all 32 carries first
// (MLP=32), then serial combine, then write carry-INs.
// ---------------------------------------------------------------------------
__global__ void __launch_bounds__(256) scan_phase2_kernel()
{
    int n = threadIdx.x;
    int b = blockIdx.x;
    const float4 mp = *(const float4*)&g_mp[n * 4];

    float2 e[NCHUNK];
    #pragma unroll
    for (int c = 0; c < NCHUNK; c++)
        e[c] = ((float2*)g_carry)[((size_t)b * NCHUNK + c) * STATE + n];

    float z = 0.0f, y = 0.0f;
    #pragma unroll
    for (int c = 0; c < NCHUNK; c++) {
        ((float2*)g_carry)[((size_t)b * NCHUNK + c) * STATE + n] = make_float2(z, y);
        float zn = fmaf(mp.x, z, fmaf(mp.y, y, e[c].x));
        float yn = fmaf(mp.z, z, fmaf(mp.w, y, e[c].y));
        z = zn; y = yn;
    }
}

// ---------------------------------------------------------------------------
// K3: fix-up + GEMM2 (out = ys @ C^T + D*x, fp16 single pass). 512 threads,
// warps 4x4. Fix per K-half computed 4-way over time quarters; y_loc is fp16.
// ---------------------------------------------------------------------------
__global__ void __launch_bounds__(512, 1)
fix_gemm2_kernel(float* __restrict__ Cout,
                 const __half* __restrict__ W,
                 const float* __restrict__ xin,
                 const float* __restrict__ Dv)
{
    constexpr int N = 128, KFULL = 256;
    constexpr int MI = 2;              // 32/16
    constexpr int NI = 4;              // 32/8
    constexpr uint32_t SA   = 0;
    constexpr uint32_t SW   = 128u * SPB;                     // 34816
    constexpr uint32_t SFIX = SW + (uint32_t)N * SPB;         // 69632

    extern __shared__ char dsm_raw[];
    char* dsm = (char*)(((uintptr_t)dsm_raw + 1023) & ~(uintptr_t)1023);
    const uint32_t dbase = smem_u32(dsm);
    float* sfix = (float*)(dsm + SFIX);

    const int tid  = threadIdx.x;
    const int lane = tid & 31;
    const int w    = tid >> 5;
    const int row0 = blockIdx.x * 128;
    const int warp_m = (w & 3) * 32;
    const int warp_n = (w >> 2) * 32;

    const int a_row = (lane & 7) + ((lane >> 3) & 1) * 8;
    const int a_k8  = (lane >> 4) * 8;
    const int b_row = (lane & 7) + (lane >> 4) * 8;
    const int b_k8  = ((lane >> 3) & 1) * 8;

    float acc[MI][NI][4];
    #pragma unroll
    for (int mi = 0; mi < MI; mi++)
        #pragma unroll
        for (int ni = 0; ni < NI; ni++)
            #pragma unroll
            for (int q = 0; q < 4; q++)
                acc[mi][ni][q] = 0.0f;

    for (int h = 0; h < 2; h++) {
        const int kh0 = h * KH;
        __syncthreads();

        // ---- fix-up: 128 states x 4 time-quarters ----
        {
            const int nl = tid & 127;
            const int q  = tid >> 7;       // 0..3
            const int n  = kh0 + nl;
            const float2 s0 = ((float2*)g_carry)[(size_t)blockIdx.x * STATE + n];
            const float4 cf = *(const float4*)&g_coef[n * 4];
            float z, y;
            if (q == 0) { z = s0.x; y = s0.y; }
            else if (q == 1) {
                const float4 m3 = *(const float4*)&g_mp32[n * 4];
                z = fmaf(m3.x, s0.x, m3.y * s0.y);
                y = fmaf(m3.z, s0.x, m3.w * s0.y);
            } else {
                const float2 e1 = ((float2*)g_e1)[(size_t)blockIdx.x * STATE + n];
                const float4 m6 = *(const float4*)&g_mp64[n * 4];
                z = fmaf(m6.x, s0.x, fmaf(m6.y, s0.y, e1.x));
                y = fmaf(m6.z, s0.x, fmaf(m6.w, s0.y, e1.y));
                if (q == 3) {
                    const float4 m3 = *(const float4*)&g_mp32[n * 4];
                    float z3 = fmaf(m3.x, z, m3.y * y);
                    float y3 = fmaf(m3.z, z, m3.w * y);
                    z = z3; y = y3;
                }
            }
            float* fp = sfix + (size_t)(q * 32) * FST + nl;
            #pragma unroll 4
            for (int t = 0; t < 32; t++) {
                float zn = fmaf(cf.x, z, cf.y * y);
                float yn = fmaf(cf.z, z, cf.w * y);
                z = zn; y = yn;
                fp[(size_t)t * FST] = y;
            }
        }
        __syncthreads();

        // ---- stage A: y_loc(fp16) + fix(fp32) -> fp16 ----
        #pragma unroll
        for (int it = 0; it < 4; it++) {
            int idx = tid + it * 512;          // 2048: 128 rows x 16 chunks of 8
            int r   = idx >> 4;
            int k   = (idx & 15) * 8;
            uint4 v = *(const uint4*)(g_ysh + (size_t)(row0 + r) * KFULL + kh0 + k);
            const __half2* h2 = (const __half2*)&v;
            const float4 f0 = *(const float4*)(sfix + (size_t)r * FST + k);
            const float4 f1 = *(const float4*)(sfix + (size_t)r * FST + k + 4);
            float2 p0 = __half22float2(h2[0]);
            float2 p1 = __half22float2(h2[1]);
            float2 p2 = __half22float2(h2[2]);
            float2 p3 = __half22float2(h2[3]);
            uint4 ov;
            ov.x = pack_h(__float2half(p0.x + f0.x), __float2half(p0.y + f0.y));
            ov.y = pack_h(__float2half(p1.x + f0.z), __float2half(p1.y + f0.w));
            ov.z = pack_h(__float2half(p2.x + f1.x), __float2half(p2.y + f1.y));
            ov.w = pack_h(__float2half(p3.x + f1.z), __float2half(p3.y + f1.w));
            *(uint4*)(dsm + SA + (uint32_t)r * SPB + (uint32_t)k * 2) = ov;
        }
        // ---- stage W (C) fp16 ----
        #pragma unroll
        for (int it = 0; it < 4; it++) {
            int idx = tid + it * 512;          // 2048 uint4
            int r   = idx >> 4;
            int k8  = (idx & 15) * 8;
            uint4 v = *(const uint4*)(W + (size_t)r * KFULL + kh0 + k8);
            uint32_t o = SW + (uint32_t)r * SPB + (uint32_t)k8 * 2;
            *(uint4*)(dsm + o) = v;
        }
        __syncthreads();

        // ---- single fp16 pass ----
        {
            const uint32_t Abase = dbase + SA;
            const uint32_t Wbase = dbase + SW;
            #pragma unroll
            for (int kk = 0; kk < KH / 16; kk++) {
                const int k0 = kk * 16;
                uint32_t af[MI][4];
                #pragma unroll
                for (int mi = 0; mi < MI; mi++) {
                    uint32_t addr = Abase
                        + (uint32_t)(warp_m + mi * 16 + a_row) * SPB
                        + (uint32_t)(k0 + a_k8) * 2;
                    LDSM_X4(af[mi][0], af[mi][1], af[mi][2], af[mi][3], addr);
                }
                uint32_t bf[NI][2];
                #pragma unroll
                for (int nj = 0; nj < NI / 2; nj++) {
                    uint32_t addr = Wbase
                        + (uint32_t)(warp_n + nj * 16 + b_row) * SPB
                        + (uint32_t)(k0 + b_k8) * 2;
                    uint32_t r0, r1, r2, r3;
                    LDSM_X4(r0, r1, r2, r3, addr);
                    bf[nj*2+0][0] = r0; bf[nj*2+0][1] = r1;
                    bf[nj*2+1][0] = r2; bf[nj*2+1][1] = r3;
                }
                #pragma unroll
                for (int mi = 0; mi < MI; mi++)
                    #pragma unroll
                    for (int ni = 0; ni < NI; ni++)
                        MMA_F16(acc[mi][ni], af[mi], bf[ni]);
            }
        }
    }

    // ---- epilogue with D*x ----
    const int rbase = row0 + warp_m + (lane >> 2);
    const int cbase = warp_n + (lane & 3) * 2;
    #pragma unroll
    for (int ni = 0; ni < NI; ni++) {
        const int col = cbase + ni * 8;
        const float d0 = Dv[col], d1 = Dv[col + 1];
        #pragma unroll
        for (int mi = 0; mi < MI; mi++) {
            const int r0 = rbase + mi * 16;
            float* p0 = Cout + (size_t)r0 * N + col;
            float* p1 = Cout + (size_t)(r0 + 8) * N + col;
            const float2 x0 = *(const float2*)(xin + (size_t)r0 * N + col);
            const float2 x1 = *(const float2*)(xin + (size_t)(r0 + 8) * N + col);
            float2 o0 = make_float2(fmaf(d0, x0.x, acc[mi][ni][0]),
                                    fmaf(d1, x0.y, acc[mi][ni][1]));
            float2 o1 = make_float2(fmaf(d0, x1.x, acc[mi][ni][2]),
                                    fmaf(d1, x1.y, acc[mi][ni][3]));
            *(float2*)p0 = o0;
            *(float2*)p1 = o1;
        }
    }
}

// ---------------------------------------------------------------------------
// kernel_launch
// Inputs: x[16,4096,128], A_diag[256], steps[256], B[256,128], C[128,256], D[128]
// ---------------------------------------------------------------------------
extern "C" void kernel_launch(void* const* d_in, const int* in_sizes, int n_in,
                              void* d_out, int out_size)
{
    const float* x      = (const float*)d_in[0];
    const float* A_diag = (const float*)d_in[1];
    const float* steps  = (const float*)d_in[2];
    const float* Bw     = (const float*)d_in[3];
    const float* Cw     = (const float*)d_in[4];
    const float* Dv     = (const float*)d_in[5];
    float* out = (float*)d_out;

    __half *b1h, *ch;
    cudaGetSymbolAddress((void**)&b1h, g_B1h);
    cudaGetSymbolAddress((void**)&ch,  g_Ch);

    // K1 SMEM covers BOTH phases: staging 104448, scan 132096+2048 (max)
    const int smem1 = 1024 + 256 * UST * 4 + 2048;                        // 135168
    const int smem3 = 1024 + 128 * SPB + 128 * SPB + 128 * FST * 4;       // 138240
    cudaFuncSetAttribute(gemm1_scan_kernel,
                         cudaFuncAttributeMaxDynamicSharedMemorySize, smem1);
    cudaFuncSetAttribute(fix_gemm2_kernel,
                         cudaFuncAttributeMaxDynamicSharedMemorySize, smem3);

    // 1. coefficients + weight fp16 conversion (single launch)
    prep_wconv_kernel<<<1 + (STATE * HIDDEN + HIDDEN * STATE) / 256, 256>>>(
        A_diag, steps, Bw, Cw);

    // 2. GEMM1 + split local scan
    gemm1_scan_kernel<<<NTILE, 512, smem1>>>(x, b1h);

    // 3. cross-chunk scan
    scan_phase2_kernel<<<BATCH, 256>>>();

    // 4. fix-up + GEMM2 (+ D*x)
    fix_gemm2_kernel<<<NTILE, 512, smem3>>>(out, ch, x, Dv);
}